// round 6
// baseline (speedup 1.0000x reference)
#include <cuda_runtime.h>
#include <cstddef>

#define NLAT 256
#define NLON 512
#define LMAX 256
#define MMAX 257
#define BATCH 16
#define CHAN 8
#define BC (BATCH*CHAN)   /* 128 */
#define BCH 64            /* bc per pass (2 passes) */

#define X_ELEMS  ((long long)BATCH*CHAN*2*NLAT*NLON)   /* 33,554,432  */
#define W_ELEMS  ((long long)2*MMAX*LMAX*NLAT)         /* 33,685,504  */
#define OUT_FLOATS_FULL 33685504LL
#define OUT_BYTES_FULL  134742016LL
#define OUT_HALF        16842752LL   /* complex element count = imag-plane offset */

// Scratch for HALF the bc range: [i][m][bc_local][k], i in {tr, ti, pr, pi}
// 4 * 257 * 64 * 256 floats = 16,842,752 floats = ~67.4 MB
__device__ float g_scratch[(size_t)4 * MMAX * BCH * NLAT];

// ---------------------------------------------------------------------------
// Stage 1: batched 512-point real-input FFT (radix-2 DIT), scale 2*pi/512.
// One block = 256 threads handles 8 consecutive k-rows of one (bc, comp).
// Covers bc in [bc0, bc0+BCH). Numerically validated identical to direct DFT.
// ---------------------------------------------------------------------------
__global__ __launch_bounds__(256)
void fft_kernel(const float* __restrict__ x, long long x_n, int bc0) {
    __shared__ float Ar[8][513];
    __shared__ float Ai[8][513];

    const int tid  = threadIdx.x;
    const int bid  = blockIdx.x;
    const int kg   = bid & 31;          // group of 8 k-rows
    const int comp = (bid >> 5) & 1;    // theta/phi
    const int bcl  = bid >> 6;          // local bc in [0,64)
    const int bc   = bc0 + bcl;
    const int k0   = kg * 8;

    const long long rowbase =
        (((long long)bc * 2 + comp) * NLAT + k0) * NLON;

    #pragma unroll
    for (int r = 0; r < 8; r++) {
        const long long rb = rowbase + (long long)r * NLON;
        for (int n = tid; n < NLON; n += 256) {
            int rv = (int)(__brev((unsigned)n) >> 23);
            long long gi = rb + n;
            Ar[r][rv] = (gi < x_n) ? x[gi] : 0.0f;
            Ai[r][rv] = 0.0f;
        }
    }
    __syncthreads();

    #pragma unroll
    for (int s = 1; s <= 9; s++) {
        const int half = 1 << (s - 1);
        const int g    = tid >> (s - 1);
        const int j    = tid & (half - 1);
        const int base = g * (half << 1) + j;
        const int p    = base + half;
        float si, co;
        __sincosf(-3.14159265358979323846f * (float)j / (float)half, &si, &co);
        #pragma unroll
        for (int r = 0; r < 8; r++) {
            float ur = Ar[r][base], ui = Ai[r][base];
            float vr = Ar[r][p],    vi = Ai[r][p];
            float tr = vr * co - vi * si;
            float ti = vr * si + vi * co;
            Ar[r][base] = ur + tr;  Ai[r][base] = ui + ti;
            Ar[r][p]    = ur - tr;  Ai[r][p]    = ui - ti;
        }
        __syncthreads();
    }

    const float SCALE = 6.283185307179586f / 512.0f;
    const size_t plane = (size_t)MMAX * BCH * NLAT;
    const size_t i_re  = (size_t)(comp * 2 + 0) * plane;
    const size_t i_im  = (size_t)(comp * 2 + 1) * plane;
    for (int idx = tid; idx < MMAX * 8; idx += 256) {
        int m = idx >> 3;
        int r = idx & 7;
        size_t off = ((size_t)m * BCH + bcl) * NLAT + (size_t)(k0 + r);
        g_scratch[i_re + off] = Ar[r][m] * SCALE;
        g_scratch[i_im + off] = Ai[r][m] * SCALE;
    }
}

// ---------------------------------------------------------------------------
// Stage 2: per-m contraction + complex recombination.
//   G[i][j][b][l] = sum_k in_i[b,k] * w_j[m,l,k]
//   out0 = (G00-G31) + i(G10+G21) ; out1 = (-G11-G20) + i(G01-G30)
// OUTPUT LAYOUT: PLANAR float32 — real plane [0, OUT_HALF), imag plane
// [OUT_HALF, 2*OUT_HALF), each indexed by cidx = ((b*2+comp)*L + l)*M + m.
// ---------------------------------------------------------------------------
#define KT 32
__global__ __launch_bounds__(256)
void contract_kernel(const float* __restrict__ w, long long w_n,
                     float* __restrict__ out, long long out_floats,
                     int bc0) {
    __shared__ float inS[4][KT][33];   // [i][k][b]
    __shared__ float wS[2][KT][65];    // [j][k][l]

    const int m    = blockIdx.y;
    const int b0l  = (blockIdx.x & 1) * 32;     // local b-tile within BCH
    const int l0   = (blockIdx.x >> 1) * 64;
    const int tid  = threadIdx.x;
    const int tx   = tid & 15;
    const int ty   = tid >> 4;

    float acc[4][2][2][4];
    #pragma unroll
    for (int i = 0; i < 4; i++)
        #pragma unroll
        for (int j = 0; j < 2; j++)
            #pragma unroll
            for (int bi = 0; bi < 2; bi++)
                #pragma unroll
                for (int li = 0; li < 4; li++)
                    acc[i][j][bi][li] = 0.0f;

    for (int kt = 0; kt < NLAT; kt += KT) {
        #pragma unroll
        for (int i = 0; i < 4; i++) {
            const size_t sbase =
                (((size_t)i * MMAX + m) * BCH + b0l) * NLAT + kt;
            for (int p = tid; p < 32 * KT; p += 256) {
                int bb = p >> 5;
                int kk = p & 31;
                inS[i][kk][bb] = g_scratch[sbase + (size_t)bb * NLAT + kk];
            }
        }
        #pragma unroll
        for (int j = 0; j < 2; j++) {
            const long long wbase =
                (((long long)j * MMAX + m) * LMAX + l0) * NLAT + kt;
            for (int p = tid; p < 64 * KT; p += 256) {
                int ll = p >> 5;
                int kk = p & 31;
                long long gi = wbase + (long long)ll * NLAT + kk;
                wS[j][kk][ll] = (gi < w_n) ? w[gi] : 0.0f;
            }
        }
        __syncthreads();

        #pragma unroll 4
        for (int kk = 0; kk < KT; kk++) {
            float a[4][2], wr[2][4];
            #pragma unroll
            for (int i = 0; i < 4; i++) {
                a[i][0] = inS[i][kk][ty * 2 + 0];
                a[i][1] = inS[i][kk][ty * 2 + 1];
            }
            #pragma unroll
            for (int j = 0; j < 2; j++)
                #pragma unroll
                for (int li = 0; li < 4; li++)
                    wr[j][li] = wS[j][kk][tx * 4 + li];
            #pragma unroll
            for (int i = 0; i < 4; i++)
                #pragma unroll
                for (int j = 0; j < 2; j++)
                    #pragma unroll
                    for (int bi = 0; bi < 2; bi++)
                        #pragma unroll
                        for (int li = 0; li < 4; li++)
                            acc[i][j][bi][li] += a[i][bi] * wr[j][li];
        }
        __syncthreads();
    }

    // Epilogue: complex recombination; PLANAR stores, guarded.
    #pragma unroll
    for (int bi = 0; bi < 2; bi++) {
        #pragma unroll
        for (int li = 0; li < 4; li++) {
            int gb = bc0 + b0l + ty * 2 + bi;     // global bc
            int l  = l0 + tx * 4 + li;
            long long c0 = (((long long)gb * 2 + 0) * LMAX + l) * MMAX + m;
            long long c1 = (((long long)gb * 2 + 1) * LMAX + l) * MMAX + m;
            float v00 = acc[0][0][bi][li] - acc[3][1][bi][li];   // re(out0)
            float v01 = acc[1][0][bi][li] + acc[2][1][bi][li];   // im(out0)
            float v10 = -acc[1][1][bi][li] - acc[2][0][bi][li];  // re(out1)
            float v11 = acc[0][1][bi][li] - acc[3][0][bi][li];   // im(out1)
            if (c0 < out_floats) out[c0] = v00;
            if (OUT_HALF + c0 < out_floats) out[OUT_HALF + c0] = v01;
            if (c1 < out_floats) out[c1] = v10;
            if (OUT_HALF + c1 < out_floats) out[OUT_HALF + c1] = v11;
        }
    }
}

// ---------------------------------------------------------------------------
extern "C" void kernel_launch(void* const* d_in, const int* in_sizes, int n_in,
                              void* d_out, int out_size) {
    const float* x = nullptr;  long long x_n = X_ELEMS;
    const float* w = nullptr;  long long w_n = W_ELEMS;

    for (int i = 0; i < n_in; i++) {
        long long sz = (long long)in_sizes[i];
        if (sz == X_ELEMS || sz == X_ELEMS * 4) x = (const float*)d_in[i];
        else if (sz == W_ELEMS || sz == W_ELEMS * 4) w = (const float*)d_in[i];
    }
    if (!x || !w) {
        x = (const float*)d_in[0];
        w = (const float*)d_in[n_in > 1 ? 1 : 0];
        long long s0 = (long long)in_sizes[0];
        long long s1 = (long long)in_sizes[n_in > 1 ? 1 : 0];
        if (s0 > X_ELEMS && s0 % 4 == 0 && s0 / 4 <= X_ELEMS) s0 /= 4;
        if (s1 > W_ELEMS && s1 % 4 == 0 && s1 / 4 <= W_ELEMS) s1 /= 4;
        x_n = s0 > 0 ? s0 : X_ELEMS;
        w_n = s1 > 0 ? s1 : W_ELEMS;
    }

    long long out_floats = (long long)out_size;
    if (out_floats == OUT_BYTES_FULL) out_floats = OUT_FLOATS_FULL;
    if (out_floats <= 0 || out_floats > OUT_FLOATS_FULL)
        out_floats = OUT_FLOATS_FULL;

    float* out = (float*)d_out;

    // Two passes over bc halves; total FFT work == single-pass (no redo).
    for (int pass = 0; pass < 2; pass++) {
        int bc0 = pass * BCH;
        fft_kernel<<<BCH * 2 * 32, 256>>>(x, x_n, bc0);
        dim3 g2(8, MMAX);
        contract_kernel<<<g2, 256>>>(w, w_n, out, out_floats, bc0);
    }
}

// round 7
// speedup vs baseline: 1.5228x; 1.5228x over previous
#include <cuda_runtime.h>
#include <cstddef>

#define NLAT 256
#define NLON 512
#define LMAX 256
#define MMAX 257
#define BATCH 16
#define CHAN 8
#define BC (BATCH*CHAN)   /* 128 */
#define BCH 64            /* bc per pass (2 passes) */

#define X_ELEMS  ((long long)BATCH*CHAN*2*NLAT*NLON)   /* 33,554,432  */
#define W_ELEMS  ((long long)2*MMAX*LMAX*NLAT)         /* 33,685,504  */
#define OUT_FLOATS_FULL 33685504LL
#define OUT_BYTES_FULL  134742016LL
#define OUT_HALF        16842752   /* complex element count = imag-plane offset */

// Scratch for HALF the bc range: [i][m][bc_local][k], i in {tr, ti, pr, pi}
// 4 * 257 * 64 * 256 floats = 16,842,752 floats = ~67.4 MB  (keep <= ~70MB!)
__device__ float g_scratch[(size_t)4 * MMAX * BCH * NLAT];

// ---------------------------------------------------------------------------
// Stage 1: batched 512-point real-input FFT (radix-2 DIT), scale 2*pi/512.
// (Unchanged from the passing R6 kernel.)
// ---------------------------------------------------------------------------
__global__ __launch_bounds__(256)
void fft_kernel(const float* __restrict__ x, long long x_n, int bc0) {
    __shared__ float Ar[8][513];
    __shared__ float Ai[8][513];

    const int tid  = threadIdx.x;
    const int bid  = blockIdx.x;
    const int kg   = bid & 31;
    const int comp = (bid >> 5) & 1;
    const int bcl  = bid >> 6;
    const int bc   = bc0 + bcl;
    const int k0   = kg * 8;

    const long long rowbase =
        (((long long)bc * 2 + comp) * NLAT + k0) * NLON;

    #pragma unroll
    for (int r = 0; r < 8; r++) {
        const long long rb = rowbase + (long long)r * NLON;
        for (int n = tid; n < NLON; n += 256) {
            int rv = (int)(__brev((unsigned)n) >> 23);
            long long gi = rb + n;
            Ar[r][rv] = (gi < x_n) ? x[gi] : 0.0f;
            Ai[r][rv] = 0.0f;
        }
    }
    __syncthreads();

    #pragma unroll
    for (int s = 1; s <= 9; s++) {
        const int half = 1 << (s - 1);
        const int g    = tid >> (s - 1);
        const int j    = tid & (half - 1);
        const int base = g * (half << 1) + j;
        const int p    = base + half;
        float si, co;
        __sincosf(-3.14159265358979323846f * (float)j / (float)half, &si, &co);
        #pragma unroll
        for (int r = 0; r < 8; r++) {
            float ur = Ar[r][base], ui = Ai[r][base];
            float vr = Ar[r][p],    vi = Ai[r][p];
            float tr = vr * co - vi * si;
            float ti = vr * si + vi * co;
            Ar[r][base] = ur + tr;  Ai[r][base] = ui + ti;
            Ar[r][p]    = ur - tr;  Ai[r][p]    = ui - ti;
        }
        __syncthreads();
    }

    const float SCALE = 6.283185307179586f / 512.0f;
    const size_t plane = (size_t)MMAX * BCH * NLAT;
    const size_t i_re  = (size_t)(comp * 2 + 0) * plane;
    const size_t i_im  = (size_t)(comp * 2 + 1) * plane;
    for (int idx = tid; idx < MMAX * 8; idx += 256) {
        int m = idx >> 3;
        int r = idx & 7;
        size_t off = ((size_t)m * BCH + bcl) * NLAT + (size_t)(k0 + r);
        g_scratch[i_re + off] = Ar[r][m] * SCALE;
        g_scratch[i_im + off] = Ai[r][m] * SCALE;
    }
}

// ---------------------------------------------------------------------------
// Stage 2 v2: per-m contraction, register-prefetch double-buffered, KT=16,
// vectorized conflict-free smem reads (LDS.64 for A, LDS.128 for W).
//   G[i][j][b][l] = sum_k in_i[b,k] * w_j[m,l,k]
// PLANAR output: re at cidx, im at OUT_HALF + cidx.
// ---------------------------------------------------------------------------
#define KT2 16
#define NTILE (NLAT / KT2)   /* 16 */

__global__ __launch_bounds__(256, 2)
void contract_kernel(const float* __restrict__ w, int w_n,
                     float* __restrict__ out, long long out_floats,
                     int bc0) {
    __shared__ float inS[4][KT2][34];   // [i][k][b]  pad 34 (8B-aligned pairs)
    __shared__ float wS[2][KT2][68];    // [j][k][l]  pad 68 (16B-aligned quads)

    const int m    = blockIdx.y;
    const int b0l  = (blockIdx.x & 1) * 32;     // local b-tile within BCH
    const int l0   = (blockIdx.x >> 1) * 64;
    const int tid  = threadIdx.x;
    const int tx   = tid & 15;                  // -> l (4 each)
    const int ty   = tid >> 4;                  // -> b (2 each)

    // Per-thread fill coordinates (constant across tiles).
    // inS element p = i*512 + bb*16 + kk ; p = t*256 + tid
    int a_kk[8], a_bb[8], a_i[8];
    int w_kk[8], w_ll[8], w_j[8];
    #pragma unroll
    for (int t = 0; t < 8; t++) {
        int p = t * 256 + tid;
        a_kk[t] = p & 15;  a_bb[t] = (p >> 4) & 31;  a_i[t] = p >> 9;
        w_kk[t] = p & 15;  w_ll[t] = (p >> 4) & 63;  w_j[t] = p >> 10;
    }
    // Global base offsets (32-bit safe: max < 2^26)
    int a_base[8], w_base[8];
    #pragma unroll
    for (int t = 0; t < 8; t++) {
        a_base[t] = ((a_i[t] * MMAX + m) * BCH + b0l + a_bb[t]) * NLAT + a_kk[t];
        w_base[t] = ((w_j[t] * MMAX + m) * LMAX + l0 + w_ll[t]) * NLAT + w_kk[t];
    }

    float acc[4][2][2][4];
    #pragma unroll
    for (int i = 0; i < 4; i++)
        #pragma unroll
        for (int j = 0; j < 2; j++)
            #pragma unroll
            for (int bi = 0; bi < 2; bi++)
                #pragma unroll
                for (int li = 0; li < 4; li++)
                    acc[i][j][bi][li] = 0.0f;

    float ra[8], rw[8];

    // Prefetch tile 0
    #pragma unroll
    for (int t = 0; t < 8; t++) ra[t] = g_scratch[a_base[t]];
    #pragma unroll
    for (int t = 0; t < 8; t++) {
        int gi = w_base[t];
        rw[t] = (gi < w_n) ? w[gi] : 0.0f;
    }

    for (int kt_i = 0; kt_i < NTILE; kt_i++) {
        __syncthreads();
        // Store staged tile into smem
        #pragma unroll
        for (int t = 0; t < 8; t++) inS[a_i[t]][a_kk[t]][a_bb[t]] = ra[t];
        #pragma unroll
        for (int t = 0; t < 8; t++) wS[w_j[t]][w_kk[t]][w_ll[t]] = rw[t];
        __syncthreads();

        // Issue next tile's global loads (overlap with compute below)
        if (kt_i + 1 < NTILE) {
            int kt = (kt_i + 1) * KT2;
            #pragma unroll
            for (int t = 0; t < 8; t++) ra[t] = g_scratch[a_base[t] + kt];
            #pragma unroll
            for (int t = 0; t < 8; t++) {
                int gi = w_base[t] + kt;
                rw[t] = (gi < w_n) ? w[gi] : 0.0f;
            }
        }

        // Compute: 16 kk x 64 FMA, vectorized smem reads
        #pragma unroll
        for (int kk = 0; kk < KT2; kk++) {
            float2 a0 = *(const float2*)&inS[0][kk][ty * 2];
            float2 a1 = *(const float2*)&inS[1][kk][ty * 2];
            float2 a2 = *(const float2*)&inS[2][kk][ty * 2];
            float2 a3 = *(const float2*)&inS[3][kk][ty * 2];
            float4 w0 = *(const float4*)&wS[0][kk][tx * 4];
            float4 w1 = *(const float4*)&wS[1][kk][tx * 4];
            const float av[4][2] = {{a0.x, a0.y}, {a1.x, a1.y},
                                    {a2.x, a2.y}, {a3.x, a3.y}};
            const float wv[2][4] = {{w0.x, w0.y, w0.z, w0.w},
                                    {w1.x, w1.y, w1.z, w1.w}};
            #pragma unroll
            for (int i = 0; i < 4; i++)
                #pragma unroll
                for (int j = 0; j < 2; j++)
                    #pragma unroll
                    for (int bi = 0; bi < 2; bi++)
                        #pragma unroll
                        for (int li = 0; li < 4; li++)
                            acc[i][j][bi][li] += av[i][bi] * wv[j][li];
        }
    }

    // Epilogue: complex recombination; PLANAR stores, guarded.
    #pragma unroll
    for (int bi = 0; bi < 2; bi++) {
        #pragma unroll
        for (int li = 0; li < 4; li++) {
            int gb = bc0 + b0l + ty * 2 + bi;     // global bc
            int l  = l0 + tx * 4 + li;
            long long c0 = (((long long)gb * 2 + 0) * LMAX + l) * MMAX + m;
            long long c1 = (((long long)gb * 2 + 1) * LMAX + l) * MMAX + m;
            float v00 = acc[0][0][bi][li] - acc[3][1][bi][li];   // re(out0)
            float v01 = acc[1][0][bi][li] + acc[2][1][bi][li];   // im(out0)
            float v10 = -acc[1][1][bi][li] - acc[2][0][bi][li];  // re(out1)
            float v11 = acc[0][1][bi][li] - acc[3][0][bi][li];   // im(out1)
            if (c0 < out_floats) out[c0] = v00;
            if (OUT_HALF + c0 < out_floats) out[OUT_HALF + c0] = v01;
            if (c1 < out_floats) out[c1] = v10;
            if (OUT_HALF + c1 < out_floats) out[OUT_HALF + c1] = v11;
        }
    }
}

// ---------------------------------------------------------------------------
extern "C" void kernel_launch(void* const* d_in, const int* in_sizes, int n_in,
                              void* d_out, int out_size) {
    const float* x = nullptr;  long long x_n = X_ELEMS;
    const float* w = nullptr;  long long w_n = W_ELEMS;

    for (int i = 0; i < n_in; i++) {
        long long sz = (long long)in_sizes[i];
        if (sz == X_ELEMS || sz == X_ELEMS * 4) x = (const float*)d_in[i];
        else if (sz == W_ELEMS || sz == W_ELEMS * 4) w = (const float*)d_in[i];
    }
    if (!x || !w) {
        x = (const float*)d_in[0];
        w = (const float*)d_in[n_in > 1 ? 1 : 0];
        long long s0 = (long long)in_sizes[0];
        long long s1 = (long long)in_sizes[n_in > 1 ? 1 : 0];
        if (s0 > X_ELEMS && s0 % 4 == 0 && s0 / 4 <= X_ELEMS) s0 /= 4;
        if (s1 > W_ELEMS && s1 % 4 == 0 && s1 / 4 <= W_ELEMS) s1 /= 4;
        x_n = s0 > 0 ? s0 : X_ELEMS;
        w_n = s1 > 0 ? s1 : W_ELEMS;
    }

    long long out_floats = (long long)out_size;
    if (out_floats == OUT_BYTES_FULL) out_floats = OUT_FLOATS_FULL;
    if (out_floats <= 0 || out_floats > OUT_FLOATS_FULL)
        out_floats = OUT_FLOATS_FULL;

    int w_n_i = (int)(w_n > W_ELEMS ? W_ELEMS : w_n);

    float* out = (float*)d_out;

    for (int pass = 0; pass < 2; pass++) {
        int bc0 = pass * BCH;
        fft_kernel<<<BCH * 2 * 32, 256>>>(x, x_n, bc0);
        dim3 g2(8, MMAX);
        contract_kernel<<<g2, 256>>>(w, w_n_i, out, out_floats, bc0);
    }
}

// round 9
// speedup vs baseline: 2.2868x; 1.5017x over previous
#include <cuda_runtime.h>
#include <cuda_bf16.h>
#include <cstdint>
#include <cstddef>

#define NLAT 256
#define NLON 512
#define LMAX 256
#define MMAX 257
#define BATCH 16
#define CHAN 8
#define BC (BATCH*CHAN)   /* 128 */

#define X_ELEMS  ((long long)BATCH*CHAN*2*NLAT*NLON)   /* 33,554,432  */
#define W_ELEMS  ((long long)2*MMAX*LMAX*NLAT)         /* 33,685,504  */
#define OUT_FLOATS_FULL 33685504LL
#define OUT_BYTES_FULL  134742016LL
#define OUT_HALF        16842752LL

// bf16 hi/lo scratch, each 67.4 MB (< 128 MiB static limit, learned R1-R4).
// Layout [plane][m][bc][k]; planes: 0=tr, 1=ti, 2=pr, 3=-pi (negated!).
__device__ __nv_bfloat16 g_hi[(size_t)4 * MMAX * BC * NLAT];
__device__ __nv_bfloat16 g_lo[(size_t)4 * MMAX * BC * NLAT];

// ---------------------------------------------------------------------------
// Stage 1: batched 512-pt real FFT (radix-2 DIT), scale 2*pi/512,
// epilogue converts to bf16 hi/lo split; comp1 imag negated.
// ---------------------------------------------------------------------------
__global__ __launch_bounds__(256)
void fft_kernel(const float* __restrict__ x, long long x_n) {
    __shared__ float Ar[8][513];
    __shared__ float Ai[8][513];

    const int tid  = threadIdx.x;
    const int bid  = blockIdx.x;
    const int kg   = bid & 31;
    const int comp = (bid >> 5) & 1;
    const int bc   = bid >> 6;
    const int k0   = kg * 8;

    const long long rowbase = (((long long)bc * 2 + comp) * NLAT + k0) * NLON;

    #pragma unroll
    for (int r = 0; r < 8; r++) {
        const long long rb = rowbase + (long long)r * NLON;
        for (int n = tid; n < NLON; n += 256) {
            int rv = (int)(__brev((unsigned)n) >> 23);
            long long gi = rb + n;
            Ar[r][rv] = (gi < x_n) ? x[gi] : 0.0f;
            Ai[r][rv] = 0.0f;
        }
    }
    __syncthreads();

    #pragma unroll
    for (int s = 1; s <= 9; s++) {
        const int half = 1 << (s - 1);
        const int g    = tid >> (s - 1);
        const int j    = tid & (half - 1);
        const int base = g * (half << 1) + j;
        const int p    = base + half;
        float si, co;
        __sincosf(-3.14159265358979323846f * (float)j / (float)half, &si, &co);
        #pragma unroll
        for (int r = 0; r < 8; r++) {
            float ur = Ar[r][base], ui = Ai[r][base];
            float vr = Ar[r][p],    vi = Ai[r][p];
            float tr = vr * co - vi * si;
            float ti = vr * si + vi * co;
            Ar[r][base] = ur + tr;  Ai[r][base] = ui + ti;
            Ar[r][p]    = ur - tr;  Ai[r][p]    = ui - ti;
        }
        __syncthreads();
    }

    const float SCALE = 6.283185307179586f / 512.0f;
    const float ISC   = comp ? -SCALE : SCALE;   // negate pi-plane imag
    const int p_re = comp * 2 + 0;
    const int p_im = comp * 2 + 1;
    for (int idx = tid; idx < MMAX * 8; idx += 256) {
        int m = idx >> 3;
        int r = idx & 7;
        int k = k0 + r;
        size_t o_re = (((size_t)p_re * MMAX + m) * BC + bc) * NLAT + k;
        size_t o_im = (((size_t)p_im * MMAX + m) * BC + bc) * NLAT + k;
        float vr = Ar[r][m] * SCALE;
        float vi = Ai[r][m] * ISC;
        __nv_bfloat16 hr = __float2bfloat16_rn(vr);
        __nv_bfloat16 hi = __float2bfloat16_rn(vi);
        g_hi[o_re] = hr;
        g_lo[o_re] = __float2bfloat16_rn(vr - __bfloat162float(hr));
        g_hi[o_im] = hi;
        g_lo[o_im] = __float2bfloat16_rn(vi - __bfloat162float(hi));
    }
}

// ---------------------------------------------------------------------------
// Stage 2: warp-level bf16 split-precision MMA (ldmatrix + mma.sync HMMA).
// CTA = (m, 32-l tile). Warp w owns bc rows [16w, 16w+16) x 32 l.
// Accs: acc0=re0, acc1=im0, acc2=-re1, acc3=im1.
// ---------------------------------------------------------------------------
#define LT 32
#define AST 40                         /* padded row stride (bf16 elems)    */
#define A_BYTES (8*128*AST*2)          /* 81920: 8 (plane,hl) x 128 x 40    */
#define B_OFF   A_BYTES
#define B_BYTES (4*32*AST*2)           /* 10240: 4 (w,hl) x 32 x 40         */
#define BUF_BYTES (A_BYTES + B_BYTES)  /* 92160                             */
#define SMEM_TOTAL (2 * BUF_BYTES)     /* 184320                            */

__device__ __forceinline__ uint32_t smem_u32(const void* p) {
    uint32_t a;
    asm("{ .reg .u64 t; cvta.to.shared.u64 t, %1; cvt.u32.u64 %0, t; }"
        : "=r"(a) : "l"(p));
    return a;
}
__device__ __forceinline__ void cp16(uint32_t dst, const void* src) {
    asm volatile("cp.async.cg.shared.global [%0], [%1], 16;"
                 :: "r"(dst), "l"(src));
}
__device__ __forceinline__ void ldm4(uint32_t* r, uint32_t addr) {
    asm volatile("ldmatrix.sync.aligned.m8n8.x4.shared.b16 {%0,%1,%2,%3}, [%4];"
                 : "=r"(r[0]), "=r"(r[1]), "=r"(r[2]), "=r"(r[3]) : "r"(addr));
}
__device__ __forceinline__ void mma16816(float* d, const uint32_t* a,
                                         const uint32_t* b) {
    asm volatile(
        "mma.sync.aligned.m16n8k16.row.col.f32.bf16.bf16.f32 "
        "{%0,%1,%2,%3},{%4,%5,%6,%7},{%8,%9},{%0,%1,%2,%3};"
        : "+f"(d[0]), "+f"(d[1]), "+f"(d[2]), "+f"(d[3])
        : "r"(a[0]), "r"(a[1]), "r"(a[2]), "r"(a[3]), "r"(b[0]), "r"(b[1]));
}

__global__ __launch_bounds__(256)
void gemm_kernel(const float* __restrict__ w, int w_n,
                 float* __restrict__ out, long long out_floats) {
    extern __shared__ char smem[];
    const uint32_t sb = smem_u32(smem);
    const int tid  = threadIdx.x;
    const int lane = tid & 31;
    const int wid  = tid >> 5;
    const int m    = blockIdx.y;
    const int l0   = blockIdx.x * LT;

    float d[4][4][4];
    #pragma unroll
    for (int a = 0; a < 4; a++)
        #pragma unroll
        for (int nf = 0; nf < 4; nf++)
            #pragma unroll
            for (int r = 0; r < 4; r++) d[a][nf][r] = 0.0f;

    // ldmatrix per-thread coordinates
    const int rowA = wid * 16 + (lane & 7) + ((lane >> 3) & 1) * 8;
    const int colA = ((lane >> 4) & 1) * 8;
    const int rowB = (lane & 7) + ((lane >> 4) & 1) * 8;
    const int colB = ((lane >> 3) & 1) * 8;

    // B register staging (2 float4 per thread per tile)
    float4 bst[2];
    int bj[2], brow[2], bcc[2];
    #pragma unroll
    for (int i = 0; i < 2; i++) {
        int c = i * 256 + tid;               // 512 float4 chunks per tile
        bj[i]   = c >> 8;
        brow[i] = (c >> 3) & 31;
        bcc[i]  = c & 7;
    }

    // A cp.async chunk mapping (16 x 16B per thread per tile)
    // chunk c: ps = c>>9, row = (c>>2)&127, cc = c&3
    #define ISSUE_A(kt, buf) do {                                              \
        _Pragma("unroll")                                                      \
        for (int i = 0; i < 16; i++) {                                         \
            int c   = i * 256 + tid;                                           \
            int ps  = c >> 9;                                                  \
            int row = (c >> 2) & 127;                                          \
            int cc  = c & 3;                                                   \
            const __nv_bfloat16* gp = ((ps & 1) ? g_lo : g_hi)                 \
                + (((size_t)(ps >> 1) * MMAX + m) * BC + row) * NLAT           \
                + (kt) * 32 + cc * 8;                                          \
            uint32_t dst = sb + (buf) * BUF_BYTES                              \
                + ((ps * 128 + row) * AST + cc * 8) * 2;                       \
            cp16(dst, gp);                                                     \
        }                                                                      \
        asm volatile("cp.async.commit_group;" ::: "memory");                   \
    } while (0)

    #define LOAD_B(kt) do {                                                    \
        _Pragma("unroll")                                                      \
        for (int i = 0; i < 2; i++) {                                          \
            int gi = ((bj[i] * MMAX + m) * LMAX + l0 + brow[i]) * NLAT         \
                   + (kt) * 32 + bcc[i] * 4;                                   \
            bst[i] = (gi + 3 < w_n) ? *(const float4*)(w + gi)                 \
                                    : make_float4(0.f, 0.f, 0.f, 0.f);         \
        }                                                                      \
    } while (0)

    #define STORE_B(buf) do {                                                  \
        _Pragma("unroll")                                                      \
        for (int i = 0; i < 2; i++) {                                          \
            float v0 = bst[i].x, v1 = bst[i].y, v2 = bst[i].z, v3 = bst[i].w;  \
            __nv_bfloat16 h0 = __float2bfloat16_rn(v0);                        \
            __nv_bfloat16 h1 = __float2bfloat16_rn(v1);                        \
            __nv_bfloat16 h2 = __float2bfloat16_rn(v2);                        \
            __nv_bfloat16 h3 = __float2bfloat16_rn(v3);                        \
            __nv_bfloat16 q0 = __float2bfloat16_rn(v0 - __bfloat162float(h0)); \
            __nv_bfloat16 q1 = __float2bfloat16_rn(v1 - __bfloat162float(h1)); \
            __nv_bfloat16 q2 = __float2bfloat16_rn(v2 - __bfloat162float(h2)); \
            __nv_bfloat16 q3 = __float2bfloat16_rn(v3 - __bfloat162float(h3)); \
            char* hb = smem + (buf) * BUF_BYTES + B_OFF                        \
                + (((bj[i] * 2 + 0) * 32 + brow[i]) * AST + bcc[i] * 4) * 2;   \
            char* lb = smem + (buf) * BUF_BYTES + B_OFF                        \
                + (((bj[i] * 2 + 1) * 32 + brow[i]) * AST + bcc[i] * 4) * 2;   \
            *(__nv_bfloat162*)(hb + 0) = __nv_bfloat162(h0, h1);               \
            *(__nv_bfloat162*)(hb + 4) = __nv_bfloat162(h2, h3);               \
            *(__nv_bfloat162*)(lb + 0) = __nv_bfloat162(q0, q1);               \
            *(__nv_bfloat162*)(lb + 4) = __nv_bfloat162(q2, q3);               \
        }                                                                      \
    } while (0)

    // product table: acc a <- sum_pr A[ap[a][pr]] * B[bp[a][pr]]
    const int ap[4][2] = {{0,3},{1,2},{1,2},{0,3}};
    const int bp[4][2] = {{0,1},{0,1},{1,0},{1,0}};

    // ---- prologue: tile 0 ----
    LOAD_B(0);
    ISSUE_A(0, 0);
    STORE_B(0);

    for (int t = 0; t < 8; t++) {
        const int buf = t & 1;
        asm volatile("cp.async.wait_group 0;" ::: "memory");
        __syncthreads();
        if (t < 7) { ISSUE_A(t + 1, buf ^ 1); LOAD_B(t + 1); }

        const uint32_t abase = sb + buf * BUF_BYTES;
        const uint32_t bbase = abase + B_OFF;
        #pragma unroll
        for (int kc = 0; kc < 2; kc++) {
            uint32_t afr[8][4];
            #pragma unroll
            for (int ps = 0; ps < 8; ps++)
                ldm4(afr[ps], abase +
                     ((ps * 128 + rowA) * AST + kc * 16 + colA) * 2);
            uint32_t bfr[4][4][2];
            #pragma unroll
            for (int js = 0; js < 4; js++)
                #pragma unroll
                for (int pr2 = 0; pr2 < 2; pr2++) {
                    uint32_t tmp[4];
                    ldm4(tmp, bbase +
                         ((js * 32 + pr2 * 16 + rowB) * AST + kc * 16 + colB) * 2);
                    bfr[js][pr2 * 2 + 0][0] = tmp[0];
                    bfr[js][pr2 * 2 + 0][1] = tmp[1];
                    bfr[js][pr2 * 2 + 1][0] = tmp[2];
                    bfr[js][pr2 * 2 + 1][1] = tmp[3];
                }
            #pragma unroll
            for (int a = 0; a < 4; a++)
                #pragma unroll
                for (int pr = 0; pr < 2; pr++) {
                    const int A = ap[a][pr], B = bp[a][pr];
                    #pragma unroll
                    for (int nf = 0; nf < 4; nf++) {
                        mma16816(d[a][nf], afr[A*2+0], bfr[B*2+0][nf]);
                        mma16816(d[a][nf], afr[A*2+0], bfr[B*2+1][nf]);
                        mma16816(d[a][nf], afr[A*2+1], bfr[B*2+0][nf]);
                    }
                }
        }
        if (t < 7) STORE_B(buf ^ 1);
    }

    // ---- epilogue: planar stores with recombination signs ----
    const int bc_b = wid * 16 + (lane >> 2);
    const int l_b  = l0 + (lane & 3) * 2;
    #pragma unroll
    for (int a = 0; a < 4; a++) {
        const int comp = a >> 1;
        const long long imof = (a == 1 || a == 3) ? OUT_HALF : 0;
        const float sgn = (a == 2) ? -1.0f : 1.0f;
        #pragma unroll
        for (int nf = 0; nf < 4; nf++)
            #pragma unroll
            for (int r = 0; r < 4; r++) {
                int row = bc_b + ((r >> 1) ? 8 : 0);
                int l   = l_b + nf * 8 + (r & 1);
                long long cidx =
                    (((long long)row * 2 + comp) * LMAX + l) * MMAX + m + imof;
                if (cidx < out_floats) out[cidx] = sgn * d[a][nf][r];
            }
    }
}

// ---------------------------------------------------------------------------
extern "C" void kernel_launch(void* const* d_in, const int* in_sizes, int n_in,
                              void* d_out, int out_size) {
    const float* x = nullptr;  long long x_n = X_ELEMS;
    const float* w = nullptr;

    for (int i = 0; i < n_in; i++) {
        long long sz = (long long)in_sizes[i];
        if (sz == X_ELEMS || sz == X_ELEMS * 4) x = (const float*)d_in[i];
        else if (sz == W_ELEMS || sz == W_ELEMS * 4) w = (const float*)d_in[i];
    }
    if (!x) x = (const float*)d_in[0];
    if (!w) w = (const float*)d_in[n_in > 1 ? 1 : 0];

    long long out_floats = (long long)out_size;
    if (out_floats == OUT_BYTES_FULL) out_floats = OUT_FLOATS_FULL;
    if (out_floats <= 0 || out_floats > OUT_FLOATS_FULL)
        out_floats = OUT_FLOATS_FULL;

    static bool attr_set = false;
    if (!attr_set) {
        cudaFuncSetAttribute(gemm_kernel,
                             cudaFuncAttributeMaxDynamicSharedMemorySize,
                             SMEM_TOTAL);
        attr_set = true;
    }

    fft_kernel<<<BC * 2 * 32, 256>>>(x, x_n);
    dim3 g2(8, MMAX);
    gemm_kernel<<<g2, 256, SMEM_TOTAL>>>(w, (int)W_ELEMS,
                                         (float*)d_out, out_floats);
}

// round 10
// speedup vs baseline: 2.5879x; 1.1317x over previous
#include <cuda_runtime.h>
#include <cuda_bf16.h>
#include <cstdint>
#include <cstddef>

#define NLAT 256
#define NLON 512
#define LMAX 256
#define MMAX 257
#define BATCH 16
#define CHAN 8
#define BC (BATCH*CHAN)   /* 128 */

#define X_ELEMS  ((long long)BATCH*CHAN*2*NLAT*NLON)   /* 33,554,432  */
#define W_ELEMS  ((long long)2*MMAX*LMAX*NLAT)         /* 33,685,504  */
#define OUT_FLOATS_FULL 33685504LL
#define OUT_BYTES_FULL  134742016LL
#define OUT_HALF        16842752LL

// bf16 hi/lo scratch, each 67.4 MB (< 128 MiB static limit, learned R1-R4).
// Layout [plane][m][bc][k]; planes: 0=tr, 1=ti, 2=pr, 3=-pi (negated!).
__device__ __nv_bfloat16 g_hi[(size_t)4 * MMAX * BC * NLAT];
__device__ __nv_bfloat16 g_lo[(size_t)4 * MMAX * BC * NLAT];

// ---------------------------------------------------------------------------
// Stage 1: batched real FFT via complex packing (two real rows per complex
// FFT), radix-2 DIT, Hermitian unpack, scale 2*pi/512, bf16 hi/lo epilogue.
// One block = 256 threads handles 8 k-rows of one (bc, comp) as 4 cFFTs.
// ---------------------------------------------------------------------------
__global__ __launch_bounds__(256)
void fft_kernel(const float* __restrict__ x, long long x_n) {
    __shared__ float Ar[4][513];
    __shared__ float Ai[4][513];

    const int tid  = threadIdx.x;
    const int bid  = blockIdx.x;
    const int kg   = bid & 31;
    const int comp = (bid >> 5) & 1;
    const int bc   = bid >> 6;
    const int k0   = kg * 8;

    const long long rowbase = (((long long)bc * 2 + comp) * NLAT + k0) * NLON;

    // Load pairs: row 2j -> real, row 2j+1 -> imag (bit-reversed order)
    #pragma unroll
    for (int j = 0; j < 4; j++) {
        const long long ra = rowbase + (long long)(2 * j) * NLON;
        const long long rb = rowbase + (long long)(2 * j + 1) * NLON;
        for (int n = tid; n < NLON; n += 256) {
            int rv = (int)(__brev((unsigned)n) >> 23);
            long long ga = ra + n, gb = rb + n;
            Ar[j][rv] = (ga < x_n) ? x[ga] : 0.0f;
            Ai[j][rv] = (gb < x_n) ? x[gb] : 0.0f;
        }
    }
    __syncthreads();

    #pragma unroll
    for (int s = 1; s <= 9; s++) {
        const int half = 1 << (s - 1);
        const int g    = tid >> (s - 1);
        const int jj   = tid & (half - 1);
        const int base = g * (half << 1) + jj;
        const int p    = base + half;
        float si, co;
        __sincosf(-3.14159265358979323846f * (float)jj / (float)half, &si, &co);
        #pragma unroll
        for (int r = 0; r < 4; r++) {
            float ur = Ar[r][base], ui = Ai[r][base];
            float vr = Ar[r][p],    vi = Ai[r][p];
            float tr = vr * co - vi * si;
            float ti = vr * si + vi * co;
            Ar[r][base] = ur + tr;  Ai[r][base] = ui + ti;
            Ar[r][p]    = ur - tr;  Ai[r][p]    = ui - ti;
        }
        __syncthreads();
    }

    // Hermitian unpack + scale + bf16 hi/lo split stores.
    const float C   = 0.5f * 6.283185307179586f / 512.0f;
    const float IC  = comp ? -C : C;           // negate pi-plane imag
    const int p_re  = comp * 2 + 0;
    const int p_im  = comp * 2 + 1;
    for (int idx = tid; idx < MMAX * 4; idx += 256) {
        int j = idx & 3;
        int m = idx >> 2;
        int mc = (512 - m) & 511;
        float zr = Ar[j][m],  zi = Ai[j][m];
        float cr = Ar[j][mc], ci = Ai[j][mc];
        // row a = k0+2j (from real part), row b = k0+2j+1 (from imag part)
        float a_re = C  * (zr + cr);
        float a_im = IC * (zi - ci);
        float b_re = C  * (zi + ci);
        float b_im = IC * (cr - zr);

        int ka = k0 + 2 * j;
        size_t o_re = (((size_t)p_re * MMAX + m) * BC + bc) * NLAT + ka;
        size_t o_im = (((size_t)p_im * MMAX + m) * BC + bc) * NLAT + ka;

        __nv_bfloat16 h;
        h = __float2bfloat16_rn(a_re);
        g_hi[o_re] = h;  g_lo[o_re] = __float2bfloat16_rn(a_re - __bfloat162float(h));
        h = __float2bfloat16_rn(b_re);
        g_hi[o_re + 1] = h;  g_lo[o_re + 1] = __float2bfloat16_rn(b_re - __bfloat162float(h));
        h = __float2bfloat16_rn(a_im);
        g_hi[o_im] = h;  g_lo[o_im] = __float2bfloat16_rn(a_im - __bfloat162float(h));
        h = __float2bfloat16_rn(b_im);
        g_hi[o_im + 1] = h;  g_lo[o_im + 1] = __float2bfloat16_rn(b_im - __bfloat162float(h));
    }
}

// ---------------------------------------------------------------------------
// Stage 2: warp-level bf16 split-precision MMA (UNCHANGED from passing R9).
// ---------------------------------------------------------------------------
#define LT 32
#define AST 40
#define A_BYTES (8*128*AST*2)
#define B_OFF   A_BYTES
#define B_BYTES (4*32*AST*2)
#define BUF_BYTES (A_BYTES + B_BYTES)
#define SMEM_TOTAL (2 * BUF_BYTES)

__device__ __forceinline__ uint32_t smem_u32(const void* p) {
    uint32_t a;
    asm("{ .reg .u64 t; cvta.to.shared.u64 t, %1; cvt.u32.u64 %0, t; }"
        : "=r"(a) : "l"(p));
    return a;
}
__device__ __forceinline__ void cp16(uint32_t dst, const void* src) {
    asm volatile("cp.async.cg.shared.global [%0], [%1], 16;"
                 :: "r"(dst), "l"(src));
}
__device__ __forceinline__ void ldm4(uint32_t* r, uint32_t addr) {
    asm volatile("ldmatrix.sync.aligned.m8n8.x4.shared.b16 {%0,%1,%2,%3}, [%4];"
                 : "=r"(r[0]), "=r"(r[1]), "=r"(r[2]), "=r"(r[3]) : "r"(addr));
}
__device__ __forceinline__ void mma16816(float* d, const uint32_t* a,
                                         const uint32_t* b) {
    asm volatile(
        "mma.sync.aligned.m16n8k16.row.col.f32.bf16.bf16.f32 "
        "{%0,%1,%2,%3},{%4,%5,%6,%7},{%8,%9},{%0,%1,%2,%3};"
        : "+f"(d[0]), "+f"(d[1]), "+f"(d[2]), "+f"(d[3])
        : "r"(a[0]), "r"(a[1]), "r"(a[2]), "r"(a[3]), "r"(b[0]), "r"(b[1]));
}

__global__ __launch_bounds__(256)
void gemm_kernel(const float* __restrict__ w, int w_n,
                 float* __restrict__ out, long long out_floats) {
    extern __shared__ char smem[];
    const uint32_t sb = smem_u32(smem);
    const int tid  = threadIdx.x;
    const int lane = tid & 31;
    const int wid  = tid >> 5;
    const int m    = blockIdx.y;
    const int l0   = blockIdx.x * LT;

    float d[4][4][4];
    #pragma unroll
    for (int a = 0; a < 4; a++)
        #pragma unroll
        for (int nf = 0; nf < 4; nf++)
            #pragma unroll
            for (int r = 0; r < 4; r++) d[a][nf][r] = 0.0f;

    const int rowA = wid * 16 + (lane & 7) + ((lane >> 3) & 1) * 8;
    const int colA = ((lane >> 4) & 1) * 8;
    const int rowB = (lane & 7) + ((lane >> 4) & 1) * 8;
    const int colB = ((lane >> 3) & 1) * 8;

    float4 bst[2];
    int bj[2], brow[2], bcc[2];
    #pragma unroll
    for (int i = 0; i < 2; i++) {
        int c = i * 256 + tid;
        bj[i]   = c >> 8;
        brow[i] = (c >> 3) & 31;
        bcc[i]  = c & 7;
    }

    #define ISSUE_A(kt, buf) do {                                              \
        _Pragma("unroll")                                                      \
        for (int i = 0; i < 16; i++) {                                         \
            int c   = i * 256 + tid;                                           \
            int ps  = c >> 9;                                                  \
            int row = (c >> 2) & 127;                                          \
            int cc  = c & 3;                                                   \
            const __nv_bfloat16* gp = ((ps & 1) ? g_lo : g_hi)                 \
                + (((size_t)(ps >> 1) * MMAX + m) * BC + row) * NLAT           \
                + (kt) * 32 + cc * 8;                                          \
            uint32_t dst = sb + (buf) * BUF_BYTES                              \
                + ((ps * 128 + row) * AST + cc * 8) * 2;                       \
            cp16(dst, gp);                                                     \
        }                                                                      \
        asm volatile("cp.async.commit_group;" ::: "memory");                   \
    } while (0)

    #define LOAD_B(kt) do {                                                    \
        _Pragma("unroll")                                                      \
        for (int i = 0; i < 2; i++) {                                          \
            int gi = ((bj[i] * MMAX + m) * LMAX + l0 + brow[i]) * NLAT         \
                   + (kt) * 32 + bcc[i] * 4;                                   \
            bst[i] = (gi + 3 < w_n) ? *(const float4*)(w + gi)                 \
                                    : make_float4(0.f, 0.f, 0.f, 0.f);         \
        }                                                                      \
    } while (0)

    #define STORE_B(buf) do {                                                  \
        _Pragma("unroll")                                                      \
        for (int i = 0; i < 2; i++) {                                          \
            float v0 = bst[i].x, v1 = bst[i].y, v2 = bst[i].z, v3 = bst[i].w;  \
            __nv_bfloat16 h0 = __float2bfloat16_rn(v0);                        \
            __nv_bfloat16 h1 = __float2bfloat16_rn(v1);                        \
            __nv_bfloat16 h2 = __float2bfloat16_rn(v2);                        \
            __nv_bfloat16 h3 = __float2bfloat16_rn(v3);                        \
            __nv_bfloat16 q0 = __float2bfloat16_rn(v0 - __bfloat162float(h0)); \
            __nv_bfloat16 q1 = __float2bfloat16_rn(v1 - __bfloat162float(h1)); \
            __nv_bfloat16 q2 = __float2bfloat16_rn(v2 - __bfloat162float(h2)); \
            __nv_bfloat16 q3 = __float2bfloat16_rn(v3 - __bfloat162float(h3)); \
            char* hb = smem + (buf) * BUF_BYTES + B_OFF                        \
                + (((bj[i] * 2 + 0) * 32 + brow[i]) * AST + bcc[i] * 4) * 2;   \
            char* lb = smem + (buf) * BUF_BYTES + B_OFF                        \
                + (((bj[i] * 2 + 1) * 32 + brow[i]) * AST + bcc[i] * 4) * 2;   \
            *(__nv_bfloat162*)(hb + 0) = __nv_bfloat162(h0, h1);               \
            *(__nv_bfloat162*)(hb + 4) = __nv_bfloat162(h2, h3);               \
            *(__nv_bfloat162*)(lb + 0) = __nv_bfloat162(q0, q1);               \
            *(__nv_bfloat162*)(lb + 4) = __nv_bfloat162(q2, q3);               \
        }                                                                      \
    } while (0)

    const int ap[4][2] = {{0,3},{1,2},{1,2},{0,3}};
    const int bp[4][2] = {{0,1},{0,1},{1,0},{1,0}};

    LOAD_B(0);
    ISSUE_A(0, 0);
    STORE_B(0);

    for (int t = 0; t < 8; t++) {
        const int buf = t & 1;
        asm volatile("cp.async.wait_group 0;" ::: "memory");
        __syncthreads();
        if (t < 7) { ISSUE_A(t + 1, buf ^ 1); LOAD_B(t + 1); }

        const uint32_t abase = sb + buf * BUF_BYTES;
        const uint32_t bbase = abase + B_OFF;
        #pragma unroll
        for (int kc = 0; kc < 2; kc++) {
            uint32_t afr[8][4];
            #pragma unroll
            for (int ps = 0; ps < 8; ps++)
                ldm4(afr[ps], abase +
                     ((ps * 128 + rowA) * AST + kc * 16 + colA) * 2);
            uint32_t bfr[4][4][2];
            #pragma unroll
            for (int js = 0; js < 4; js++)
                #pragma unroll
                for (int pr2 = 0; pr2 < 2; pr2++) {
                    uint32_t tmp[4];
                    ldm4(tmp, bbase +
                         ((js * 32 + pr2 * 16 + rowB) * AST + kc * 16 + colB) * 2);
                    bfr[js][pr2 * 2 + 0][0] = tmp[0];
                    bfr[js][pr2 * 2 + 0][1] = tmp[1];
                    bfr[js][pr2 * 2 + 1][0] = tmp[2];
                    bfr[js][pr2 * 2 + 1][1] = tmp[3];
                }
            #pragma unroll
            for (int a = 0; a < 4; a++)
                #pragma unroll
                for (int pr = 0; pr < 2; pr++) {
                    const int A = ap[a][pr], B = bp[a][pr];
                    #pragma unroll
                    for (int nf = 0; nf < 4; nf++) {
                        mma16816(d[a][nf], afr[A*2+0], bfr[B*2+0][nf]);
                        mma16816(d[a][nf], afr[A*2+0], bfr[B*2+1][nf]);
                        mma16816(d[a][nf], afr[A*2+1], bfr[B*2+0][nf]);
                    }
                }
        }
        if (t < 7) STORE_B(buf ^ 1);
    }

    const int bc_b = wid * 16 + (lane >> 2);
    const int l_b  = l0 + (lane & 3) * 2;
    #pragma unroll
    for (int a = 0; a < 4; a++) {
        const int comp = a >> 1;
        const long long imof = (a == 1 || a == 3) ? OUT_HALF : 0;
        const float sgn = (a == 2) ? -1.0f : 1.0f;
        #pragma unroll
        for (int nf = 0; nf < 4; nf++)
            #pragma unroll
            for (int r = 0; r < 4; r++) {
                int row = bc_b + ((r >> 1) ? 8 : 0);
                int l   = l_b + nf * 8 + (r & 1);
                long long cidx =
                    (((long long)row * 2 + comp) * LMAX + l) * MMAX + m + imof;
                if (cidx < out_floats) out[cidx] = sgn * d[a][nf][r];
            }
    }
}

// ---------------------------------------------------------------------------
extern "C" void kernel_launch(void* const* d_in, const int* in_sizes, int n_in,
                              void* d_out, int out_size) {
    const float* x = nullptr;  long long x_n = X_ELEMS;
    const float* w = nullptr;

    for (int i = 0; i < n_in; i++) {
        long long sz = (long long)in_sizes[i];
        if (sz == X_ELEMS || sz == X_ELEMS * 4) x = (const float*)d_in[i];
        else if (sz == W_ELEMS || sz == W_ELEMS * 4) w = (const float*)d_in[i];
    }
    if (!x) x = (const float*)d_in[0];
    if (!w) w = (const float*)d_in[n_in > 1 ? 1 : 0];

    long long out_floats = (long long)out_size;
    if (out_floats == OUT_BYTES_FULL) out_floats = OUT_FLOATS_FULL;
    if (out_floats <= 0 || out_floats > OUT_FLOATS_FULL)
        out_floats = OUT_FLOATS_FULL;

    static bool attr_set = false;
    if (!attr_set) {
        cudaFuncSetAttribute(gemm_kernel,
                             cudaFuncAttributeMaxDynamicSharedMemorySize,
                             SMEM_TOTAL);
        attr_set = true;
    }

    fft_kernel<<<BC * 2 * 32, 256>>>(x, x_n);
    dim3 g2(8, MMAX);
    gemm_kernel<<<g2, 256, SMEM_TOTAL>>>(w, (int)W_ELEMS,
                                         (float*)d_out, out_floats);
}

// round 11
// speedup vs baseline: 2.6081x; 1.0078x over previous
#include <cuda_runtime.h>
#include <cuda_bf16.h>
#include <cstdint>
#include <cstddef>

#define NLAT 256
#define NLON 512
#define LMAX 256
#define MMAX 257
#define BATCH 16
#define CHAN 8
#define BC (BATCH*CHAN)   /* 128 */

#define X_ELEMS  ((long long)BATCH*CHAN*2*NLAT*NLON)   /* 33,554,432  */
#define W_ELEMS  ((long long)2*MMAX*LMAX*NLAT)         /* 33,685,504  */
#define OUT_FLOATS_FULL 33685504LL
#define OUT_BYTES_FULL  134742016LL
#define OUT_HALF        16842752LL

// bf16 hi/lo scratch, each 67.4 MB (< 128 MiB static limit, learned R1-R4).
// Layout [plane][m][bc][k]; planes: 0=tr, 1=ti, 2=pr, 3=-pi (negated!).
__device__ __nv_bfloat16 g_hi[(size_t)4 * MMAX * BC * NLAT];
__device__ __nv_bfloat16 g_lo[(size_t)4 * MMAX * BC * NLAT];

// ---------------------------------------------------------------------------
// Stage 1: batched real FFT via complex packing (two real rows per complex
// FFT), radix-2 DIT, Hermitian unpack, scale 2*pi/512, bf16 hi/lo epilogue.
// (UNCHANGED from passing R10.)
// ---------------------------------------------------------------------------
__global__ __launch_bounds__(256)
void fft_kernel(const float* __restrict__ x, long long x_n) {
    __shared__ float Ar[4][513];
    __shared__ float Ai[4][513];

    const int tid  = threadIdx.x;
    const int bid  = blockIdx.x;
    const int kg   = bid & 31;
    const int comp = (bid >> 5) & 1;
    const int bc   = bid >> 6;
    const int k0   = kg * 8;

    const long long rowbase = (((long long)bc * 2 + comp) * NLAT + k0) * NLON;

    #pragma unroll
    for (int j = 0; j < 4; j++) {
        const long long ra = rowbase + (long long)(2 * j) * NLON;
        const long long rb = rowbase + (long long)(2 * j + 1) * NLON;
        for (int n = tid; n < NLON; n += 256) {
            int rv = (int)(__brev((unsigned)n) >> 23);
            long long ga = ra + n, gb = rb + n;
            Ar[j][rv] = (ga < x_n) ? x[ga] : 0.0f;
            Ai[j][rv] = (gb < x_n) ? x[gb] : 0.0f;
        }
    }
    __syncthreads();

    #pragma unroll
    for (int s = 1; s <= 9; s++) {
        const int half = 1 << (s - 1);
        const int g    = tid >> (s - 1);
        const int jj   = tid & (half - 1);
        const int base = g * (half << 1) + jj;
        const int p    = base + half;
        float si, co;
        __sincosf(-3.14159265358979323846f * (float)jj / (float)half, &si, &co);
        #pragma unroll
        for (int r = 0; r < 4; r++) {
            float ur = Ar[r][base], ui = Ai[r][base];
            float vr = Ar[r][p],    vi = Ai[r][p];
            float tr = vr * co - vi * si;
            float ti = vr * si + vi * co;
            Ar[r][base] = ur + tr;  Ai[r][base] = ui + ti;
            Ar[r][p]    = ur - tr;  Ai[r][p]    = ui - ti;
        }
        __syncthreads();
    }

    const float C   = 0.5f * 6.283185307179586f / 512.0f;
    const float IC  = comp ? -C : C;
    const int p_re  = comp * 2 + 0;
    const int p_im  = comp * 2 + 1;
    for (int idx = tid; idx < MMAX * 4; idx += 256) {
        int j = idx & 3;
        int m = idx >> 2;
        int mc = (512 - m) & 511;
        float zr = Ar[j][m],  zi = Ai[j][m];
        float cr = Ar[j][mc], ci = Ai[j][mc];
        float a_re = C  * (zr + cr);
        float a_im = IC * (zi - ci);
        float b_re = C  * (zi + ci);
        float b_im = IC * (cr - zr);

        int ka = k0 + 2 * j;
        size_t o_re = (((size_t)p_re * MMAX + m) * BC + bc) * NLAT + ka;
        size_t o_im = (((size_t)p_im * MMAX + m) * BC + bc) * NLAT + ka;

        __nv_bfloat16 h;
        h = __float2bfloat16_rn(a_re);
        g_hi[o_re] = h;  g_lo[o_re] = __float2bfloat16_rn(a_re - __bfloat162float(h));
        h = __float2bfloat16_rn(b_re);
        g_hi[o_re + 1] = h;  g_lo[o_re + 1] = __float2bfloat16_rn(b_re - __bfloat162float(h));
        h = __float2bfloat16_rn(a_im);
        g_hi[o_im] = h;  g_lo[o_im] = __float2bfloat16_rn(a_im - __bfloat162float(h));
        h = __float2bfloat16_rn(b_im);
        g_hi[o_im + 1] = h;  g_lo[o_im + 1] = __float2bfloat16_rn(b_im - __bfloat162float(h));
    }
}

// ---------------------------------------------------------------------------
// Stage 2: warp-level bf16 split-precision MMA.
// R11 change: MMA issue order (term, pr, a, nf) — each accumulator touched
// once per 16-MMA sweep, breaking the 3-deep RAW chains of R9/R10.
// ---------------------------------------------------------------------------
#define LT 32
#define AST 40
#define A_BYTES (8*128*AST*2)
#define B_OFF   A_BYTES
#define B_BYTES (4*32*AST*2)
#define BUF_BYTES (A_BYTES + B_BYTES)
#define SMEM_TOTAL (2 * BUF_BYTES)

__device__ __forceinline__ uint32_t smem_u32(const void* p) {
    uint32_t a;
    asm("{ .reg .u64 t; cvta.to.shared.u64 t, %1; cvt.u32.u64 %0, t; }"
        : "=r"(a) : "l"(p));
    return a;
}
__device__ __forceinline__ void cp16(uint32_t dst, const void* src) {
    asm volatile("cp.async.cg.shared.global [%0], [%1], 16;"
                 :: "r"(dst), "l"(src));
}
__device__ __forceinline__ void ldm4(uint32_t* r, uint32_t addr) {
    asm volatile("ldmatrix.sync.aligned.m8n8.x4.shared.b16 {%0,%1,%2,%3}, [%4];"
                 : "=r"(r[0]), "=r"(r[1]), "=r"(r[2]), "=r"(r[3]) : "r"(addr));
}
__device__ __forceinline__ void mma16816(float* d, const uint32_t* a,
                                         const uint32_t* b) {
    asm volatile(
        "mma.sync.aligned.m16n8k16.row.col.f32.bf16.bf16.f32 "
        "{%0,%1,%2,%3},{%4,%5,%6,%7},{%8,%9},{%0,%1,%2,%3};"
        : "+f"(d[0]), "+f"(d[1]), "+f"(d[2]), "+f"(d[3])
        : "r"(a[0]), "r"(a[1]), "r"(a[2]), "r"(a[3]), "r"(b[0]), "r"(b[1]));
}

__global__ __launch_bounds__(256)
void gemm_kernel(const float* __restrict__ w, int w_n,
                 float* __restrict__ out, long long out_floats) {
    extern __shared__ char smem[];
    const uint32_t sb = smem_u32(smem);
    const int tid  = threadIdx.x;
    const int lane = tid & 31;
    const int wid  = tid >> 5;
    const int m    = blockIdx.y;
    const int l0   = blockIdx.x * LT;

    float d[4][4][4];
    #pragma unroll
    for (int a = 0; a < 4; a++)
        #pragma unroll
        for (int nf = 0; nf < 4; nf++)
            #pragma unroll
            for (int r = 0; r < 4; r++) d[a][nf][r] = 0.0f;

    const int rowA = wid * 16 + (lane & 7) + ((lane >> 3) & 1) * 8;
    const int colA = ((lane >> 4) & 1) * 8;
    const int rowB = (lane & 7) + ((lane >> 4) & 1) * 8;
    const int colB = ((lane >> 3) & 1) * 8;

    float4 bst[2];
    int bj[2], brow[2], bcc[2];
    #pragma unroll
    for (int i = 0; i < 2; i++) {
        int c = i * 256 + tid;
        bj[i]   = c >> 8;
        brow[i] = (c >> 3) & 31;
        bcc[i]  = c & 7;
    }

    #define ISSUE_A(kt, buf) do {                                              \
        _Pragma("unroll")                                                      \
        for (int i = 0; i < 16; i++) {                                         \
            int c   = i * 256 + tid;                                           \
            int ps  = c >> 9;                                                  \
            int row = (c >> 2) & 127;                                          \
            int cc  = c & 3;                                                   \
            const __nv_bfloat16* gp = ((ps & 1) ? g_lo : g_hi)                 \
                + (((size_t)(ps >> 1) * MMAX + m) * BC + row) * NLAT           \
                + (kt) * 32 + cc * 8;                                          \
            uint32_t dst = sb + (buf) * BUF_BYTES                              \
                + ((ps * 128 + row) * AST + cc * 8) * 2;                       \
            cp16(dst, gp);                                                     \
        }                                                                      \
        asm volatile("cp.async.commit_group;" ::: "memory");                   \
    } while (0)

    #define LOAD_B(kt) do {                                                    \
        _Pragma("unroll")                                                      \
        for (int i = 0; i < 2; i++) {                                          \
            int gi = ((bj[i] * MMAX + m) * LMAX + l0 + brow[i]) * NLAT         \
                   + (kt) * 32 + bcc[i] * 4;                                   \
            bst[i] = (gi + 3 < w_n) ? *(const float4*)(w + gi)                 \
                                    : make_float4(0.f, 0.f, 0.f, 0.f);         \
        }                                                                      \
    } while (0)

    #define STORE_B(buf) do {                                                  \
        _Pragma("unroll")                                                      \
        for (int i = 0; i < 2; i++) {                                          \
            float v0 = bst[i].x, v1 = bst[i].y, v2 = bst[i].z, v3 = bst[i].w;  \
            __nv_bfloat16 h0 = __float2bfloat16_rn(v0);                        \
            __nv_bfloat16 h1 = __float2bfloat16_rn(v1);                        \
            __nv_bfloat16 h2 = __float2bfloat16_rn(v2);                        \
            __nv_bfloat16 h3 = __float2bfloat16_rn(v3);                        \
            __nv_bfloat16 q0 = __float2bfloat16_rn(v0 - __bfloat162float(h0)); \
            __nv_bfloat16 q1 = __float2bfloat16_rn(v1 - __bfloat162float(h1)); \
            __nv_bfloat16 q2 = __float2bfloat16_rn(v2 - __bfloat162float(h2)); \
            __nv_bfloat16 q3 = __float2bfloat16_rn(v3 - __bfloat162float(h3)); \
            char* hb = smem + (buf) * BUF_BYTES + B_OFF                        \
                + (((bj[i] * 2 + 0) * 32 + brow[i]) * AST + bcc[i] * 4) * 2;   \
            char* lb = smem + (buf) * BUF_BYTES + B_OFF                        \
                + (((bj[i] * 2 + 1) * 32 + brow[i]) * AST + bcc[i] * 4) * 2;   \
            *(__nv_bfloat162*)(hb + 0) = __nv_bfloat162(h0, h1);               \
            *(__nv_bfloat162*)(hb + 4) = __nv_bfloat162(h2, h3);               \
            *(__nv_bfloat162*)(lb + 0) = __nv_bfloat162(q0, q1);               \
            *(__nv_bfloat162*)(lb + 4) = __nv_bfloat162(q2, q3);               \
        }                                                                      \
    } while (0)

    const int ap[4][2] = {{0,3},{1,2},{1,2},{0,3}};
    const int bp[4][2] = {{0,1},{0,1},{1,0},{1,0}};

    LOAD_B(0);
    ISSUE_A(0, 0);
    STORE_B(0);

    for (int t = 0; t < 8; t++) {
        const int buf = t & 1;
        asm volatile("cp.async.wait_group 0;" ::: "memory");
        __syncthreads();
        if (t < 7) { ISSUE_A(t + 1, buf ^ 1); LOAD_B(t + 1); }

        const uint32_t abase = sb + buf * BUF_BYTES;
        const uint32_t bbase = abase + B_OFF;
        #pragma unroll
        for (int kc = 0; kc < 2; kc++) {
            uint32_t afr[8][4];
            #pragma unroll
            for (int ps = 0; ps < 8; ps++)
                ldm4(afr[ps], abase +
                     ((ps * 128 + rowA) * AST + kc * 16 + colA) * 2);
            uint32_t bfr[4][4][2];
            #pragma unroll
            for (int js = 0; js < 4; js++)
                #pragma unroll
                for (int pr2 = 0; pr2 < 2; pr2++) {
                    uint32_t tmp[4];
                    ldm4(tmp, bbase +
                         ((js * 32 + pr2 * 16 + rowB) * AST + kc * 16 + colB) * 2);
                    bfr[js][pr2 * 2 + 0][0] = tmp[0];
                    bfr[js][pr2 * 2 + 0][1] = tmp[1];
                    bfr[js][pr2 * 2 + 1][0] = tmp[2];
                    bfr[js][pr2 * 2 + 1][1] = tmp[3];
                }
            // term-major sweep: 32 independent MMAs per term, each
            // accumulator touched once per 16-MMA half-sweep.
            #pragma unroll
            for (int term = 0; term < 3; term++) {
                const int ahl = (term == 2) ? 1 : 0;   // lo*hi on term 2
                const int bhl = (term == 1) ? 1 : 0;   // hi*lo on term 1
                #pragma unroll
                for (int pr = 0; pr < 2; pr++) {
                    #pragma unroll
                    for (int a = 0; a < 4; a++) {
                        const int A = ap[a][pr], B = bp[a][pr];
                        #pragma unroll
                        for (int nf = 0; nf < 4; nf++)
                            mma16816(d[a][nf], afr[A*2+ahl], bfr[B*2+bhl][nf]);
                    }
                }
            }
        }
        if (t < 7) STORE_B(buf ^ 1);
    }

    const int bc_b = wid * 16 + (lane >> 2);
    const int l_b  = l0 + (lane & 3) * 2;
    #pragma unroll
    for (int a = 0; a < 4; a++) {
        const int comp = a >> 1;
        const long long imof = (a == 1 || a == 3) ? OUT_HALF : 0;
        const float sgn = (a == 2) ? -1.0f : 1.0f;
        #pragma unroll
        for (int nf = 0; nf < 4; nf++)
            #pragma unroll
            for (int r = 0; r < 4; r++) {
                int row = bc_b + ((r >> 1) ? 8 : 0);
                int l   = l_b + nf * 8 + (r & 1);
                long long cidx =
                    (((long long)row * 2 + comp) * LMAX + l) * MMAX + m + imof;
                if (cidx < out_floats) out[cidx] = sgn * d[a][nf][r];
            }
    }
}

// ---------------------------------------------------------------------------
extern "C" void kernel_launch(void* const* d_in, const int* in_sizes, int n_in,
                              void* d_out, int out_size) {
    const float* x = nullptr;  long long x_n = X_ELEMS;
    const float* w = nullptr;

    for (int i = 0; i < n_in; i++) {
        long long sz = (long long)in_sizes[i];
        if (sz == X_ELEMS || sz == X_ELEMS * 4) x = (const float*)d_in[i];
        else if (sz == W_ELEMS || sz == W_ELEMS * 4) w = (const float*)d_in[i];
    }
    if (!x) x = (const float*)d_in[0];
    if (!w) w = (const float*)d_in[n_in > 1 ? 1 : 0];

    long long out_floats = (long long)out_size;
    if (out_floats == OUT_BYTES_FULL) out_floats = OUT_FLOATS_FULL;
    if (out_floats <= 0 || out_floats > OUT_FLOATS_FULL)
        out_floats = OUT_FLOATS_FULL;

    static bool attr_set = false;
    if (!attr_set) {
        cudaFuncSetAttribute(gemm_kernel,
                             cudaFuncAttributeMaxDynamicSharedMemorySize,
                             SMEM_TOTAL);
        attr_set = true;
    }

    fft_kernel<<<BC * 2 * 32, 256>>>(x, x_n);
    dim3 g2(8, MMAX);
    gemm_kernel<<<g2, 256, SMEM_TOTAL>>>(w, (int)W_ELEMS,
                                         (float*)d_out, out_floats);
}

// round 12
// speedup vs baseline: 2.6406x; 1.0124x over previous
#include <cuda_runtime.h>
#include <cuda_bf16.h>
#include <cstdint>
#include <cstddef>

#define NLAT 256
#define NLON 512
#define LMAX 256
#define MMAX 257
#define BATCH 16
#define CHAN 8
#define BC (BATCH*CHAN)   /* 128 */

#define X_ELEMS  ((long long)BATCH*CHAN*2*NLAT*NLON)   /* 33,554,432  */
#define W_ELEMS  ((long long)2*MMAX*LMAX*NLAT)         /* 33,685,504  */
#define OUT_FLOATS_FULL 33685504LL
#define OUT_BYTES_FULL  134742016LL
#define OUT_HALF        16842752LL

// bf16 hi/lo scratch, each 67.4 MB (< 128 MiB static limit, learned R1-R4).
// Layout [plane][m][bc][k]; planes: 0=tr, 1=ti, 2=pr, 3=-pi (negated!).
__device__ __nv_bfloat16 g_hi[(size_t)4 * MMAX * BC * NLAT];
__device__ __nv_bfloat16 g_lo[(size_t)4 * MMAX * BC * NLAT];

// ---------------------------------------------------------------------------
// Stage 1: batched real FFT via complex packing, radix-2 DIT, Hermitian
// unpack, scale 2*pi/512, bf16 hi/lo epilogue. (UNCHANGED from passing R10.)
// ---------------------------------------------------------------------------
__global__ __launch_bounds__(256)
void fft_kernel(const float* __restrict__ x, long long x_n) {
    __shared__ float Ar[4][513];
    __shared__ float Ai[4][513];

    const int tid  = threadIdx.x;
    const int bid  = blockIdx.x;
    const int kg   = bid & 31;
    const int comp = (bid >> 5) & 1;
    const int bc   = bid >> 6;
    const int k0   = kg * 8;

    const long long rowbase = (((long long)bc * 2 + comp) * NLAT + k0) * NLON;

    #pragma unroll
    for (int j = 0; j < 4; j++) {
        const long long ra = rowbase + (long long)(2 * j) * NLON;
        const long long rb = rowbase + (long long)(2 * j + 1) * NLON;
        for (int n = tid; n < NLON; n += 256) {
            int rv = (int)(__brev((unsigned)n) >> 23);
            long long ga = ra + n, gb = rb + n;
            Ar[j][rv] = (ga < x_n) ? x[ga] : 0.0f;
            Ai[j][rv] = (gb < x_n) ? x[gb] : 0.0f;
        }
    }
    __syncthreads();

    #pragma unroll
    for (int s = 1; s <= 9; s++) {
        const int half = 1 << (s - 1);
        const int g    = tid >> (s - 1);
        const int jj   = tid & (half - 1);
        const int base = g * (half << 1) + jj;
        const int p    = base + half;
        float si, co;
        __sincosf(-3.14159265358979323846f * (float)jj / (float)half, &si, &co);
        #pragma unroll
        for (int r = 0; r < 4; r++) {
            float ur = Ar[r][base], ui = Ai[r][base];
            float vr = Ar[r][p],    vi = Ai[r][p];
            float tr = vr * co - vi * si;
            float ti = vr * si + vi * co;
            Ar[r][base] = ur + tr;  Ai[r][base] = ui + ti;
            Ar[r][p]    = ur - tr;  Ai[r][p]    = ui - ti;
        }
        __syncthreads();
    }

    const float C   = 0.5f * 6.283185307179586f / 512.0f;
    const float IC  = comp ? -C : C;
    const int p_re  = comp * 2 + 0;
    const int p_im  = comp * 2 + 1;
    for (int idx = tid; idx < MMAX * 4; idx += 256) {
        int j = idx & 3;
        int m = idx >> 2;
        int mc = (512 - m) & 511;
        float zr = Ar[j][m],  zi = Ai[j][m];
        float cr = Ar[j][mc], ci = Ai[j][mc];
        float a_re = C  * (zr + cr);
        float a_im = IC * (zi - ci);
        float b_re = C  * (zi + ci);
        float b_im = IC * (cr - zr);

        int ka = k0 + 2 * j;
        size_t o_re = (((size_t)p_re * MMAX + m) * BC + bc) * NLAT + ka;
        size_t o_im = (((size_t)p_im * MMAX + m) * BC + bc) * NLAT + ka;

        __nv_bfloat16 h;
        h = __float2bfloat16_rn(a_re);
        g_hi[o_re] = h;  g_lo[o_re] = __float2bfloat16_rn(a_re - __bfloat162float(h));
        h = __float2bfloat16_rn(b_re);
        g_hi[o_re + 1] = h;  g_lo[o_re + 1] = __float2bfloat16_rn(b_re - __bfloat162float(h));
        h = __float2bfloat16_rn(a_im);
        g_hi[o_im] = h;  g_lo[o_im] = __float2bfloat16_rn(a_im - __bfloat162float(h));
        h = __float2bfloat16_rn(b_im);
        g_hi[o_im + 1] = h;  g_lo[o_im + 1] = __float2bfloat16_rn(b_im - __bfloat162float(h));
    }
}

// ---------------------------------------------------------------------------
// Stage 2: warp-level bf16 split-precision MMA.
// R12: KT=16, smem 108 KB/CTA, 2 CTAs/SM; A-fragments staged in two waves
// (hi for terms 0-1, lo for term 2) to fit 128 regs.
// ---------------------------------------------------------------------------
#define LT 32
#define KT 16
#define NTILE (NLAT / KT)              /* 16 */
#define AST 24                          /* row stride elems (48 B): 16B-aligned,
                                           granules 0,3,6,1,4,7,2,5 = no conflict */
#define A_BYTES (8*128*AST*2)           /* 49152 */
#define B_OFF   A_BYTES
#define B_BYTES (4*32*AST*2)            /* 6144  */
#define BUF_BYTES (A_BYTES + B_BYTES)   /* 55296 */
#define SMEM_TOTAL (2 * BUF_BYTES)      /* 110592 = 108 KB */

__device__ __forceinline__ uint32_t smem_u32(const void* p) {
    uint32_t a;
    asm("{ .reg .u64 t; cvta.to.shared.u64 t, %1; cvt.u32.u64 %0, t; }"
        : "=r"(a) : "l"(p));
    return a;
}
__device__ __forceinline__ void cp16(uint32_t dst, const void* src) {
    asm volatile("cp.async.cg.shared.global [%0], [%1], 16;"
                 :: "r"(dst), "l"(src));
}
__device__ __forceinline__ void ldm4(uint32_t* r, uint32_t addr) {
    asm volatile("ldmatrix.sync.aligned.m8n8.x4.shared.b16 {%0,%1,%2,%3}, [%4];"
                 : "=r"(r[0]), "=r"(r[1]), "=r"(r[2]), "=r"(r[3]) : "r"(addr));
}
__device__ __forceinline__ void mma16816(float* d, const uint32_t* a,
                                         const uint32_t* b) {
    asm volatile(
        "mma.sync.aligned.m16n8k16.row.col.f32.bf16.bf16.f32 "
        "{%0,%1,%2,%3},{%4,%5,%6,%7},{%8,%9},{%0,%1,%2,%3};"
        : "+f"(d[0]), "+f"(d[1]), "+f"(d[2]), "+f"(d[3])
        : "r"(a[0]), "r"(a[1]), "r"(a[2]), "r"(a[3]), "r"(b[0]), "r"(b[1]));
}

__global__ __launch_bounds__(256, 2)
void gemm_kernel(const float* __restrict__ w, int w_n,
                 float* __restrict__ out, long long out_floats) {
    extern __shared__ char smem[];
    const uint32_t sb = smem_u32(smem);
    const int tid  = threadIdx.x;
    const int lane = tid & 31;
    const int wid  = tid >> 5;
    const int m    = blockIdx.y;
    const int l0   = blockIdx.x * LT;

    float d[4][4][4];
    #pragma unroll
    for (int a = 0; a < 4; a++)
        #pragma unroll
        for (int nf = 0; nf < 4; nf++)
            #pragma unroll
            for (int r = 0; r < 4; r++) d[a][nf][r] = 0.0f;

    const int rowA = wid * 16 + (lane & 7) + ((lane >> 3) & 1) * 8;
    const int colA = ((lane >> 4) & 1) * 8;
    const int rowB = (lane & 7) + ((lane >> 4) & 1) * 8;
    const int colB = ((lane >> 3) & 1) * 8;

    // B staging: 1 float4 per thread per tile (2 wpl x 32 rows x 4 float4).
    float4 bst;
    const int bj   = tid >> 7;
    const int brow = (tid >> 2) & 31;
    const int bcc  = tid & 3;

    // A cp.async: 8 x 16B chunks per thread per tile.
    // chunk c in [0,2048): ps=c>>8 (plane*2+hl), row=(c>>1)&127, cc=c&1.
    #define ISSUE_A(kt, buf) do {                                              \
        _Pragma("unroll")                                                      \
        for (int i = 0; i < 8; i++) {                                          \
            int c   = i * 256 + tid;                                           \
            int ps  = c >> 8;                                                  \
            int row = (c >> 1) & 127;                                          \
            int cc  = c & 1;                                                   \
            const __nv_bfloat16* gp = ((ps & 1) ? g_lo : g_hi)                 \
                + (((size_t)(ps >> 1) * MMAX + m) * BC + row) * NLAT           \
                + (kt) * KT + cc * 8;                                          \
            uint32_t dst = sb + (buf) * BUF_BYTES                              \
                + ((ps * 128 + row) * AST + cc * 8) * 2;                       \
            cp16(dst, gp);                                                     \
        }                                                                      \
        asm volatile("cp.async.commit_group;" ::: "memory");                   \
    } while (0)

    #define LOAD_B(kt) do {                                                    \
        int gi = ((bj * MMAX + m) * LMAX + l0 + brow) * NLAT                   \
               + (kt) * KT + bcc * 4;                                          \
        bst = (gi + 3 < w_n) ? *(const float4*)(w + gi)                        \
                             : make_float4(0.f, 0.f, 0.f, 0.f);                \
    } while (0)

    #define STORE_B(buf) do {                                                  \
        float v0 = bst.x, v1 = bst.y, v2 = bst.z, v3 = bst.w;                  \
        __nv_bfloat16 h0 = __float2bfloat16_rn(v0);                            \
        __nv_bfloat16 h1 = __float2bfloat16_rn(v1);                            \
        __nv_bfloat16 h2 = __float2bfloat16_rn(v2);                            \
        __nv_bfloat16 h3 = __float2bfloat16_rn(v3);                            \
        __nv_bfloat16 q0 = __float2bfloat16_rn(v0 - __bfloat162float(h0));     \
        __nv_bfloat16 q1 = __float2bfloat16_rn(v1 - __bfloat162float(h1));     \
        __nv_bfloat16 q2 = __float2bfloat16_rn(v2 - __bfloat162float(h2));     \
        __nv_bfloat16 q3 = __float2bfloat16_rn(v3 - __bfloat162float(h3));     \
        char* hb = smem + (buf) * BUF_BYTES + B_OFF                            \
            + (((bj * 2 + 0) * 32 + brow) * AST + bcc * 4) * 2;                \
        char* lb = smem + (buf) * BUF_BYTES + B_OFF                            \
            + (((bj * 2 + 1) * 32 + brow) * AST + bcc * 4) * 2;                \
        *(__nv_bfloat162*)(hb + 0) = __nv_bfloat162(h0, h1);                   \
        *(__nv_bfloat162*)(hb + 4) = __nv_bfloat162(h2, h3);                   \
        *(__nv_bfloat162*)(lb + 0) = __nv_bfloat162(q0, q1);                   \
        *(__nv_bfloat162*)(lb + 4) = __nv_bfloat162(q2, q3);                   \
    } while (0)

    const int ap[4][2] = {{0,3},{1,2},{1,2},{0,3}};
    const int bp[4][2] = {{0,1},{0,1},{1,0},{1,0}};

    LOAD_B(0);
    ISSUE_A(0, 0);
    STORE_B(0);

    for (int t = 0; t < NTILE; t++) {
        const int buf = t & 1;
        asm volatile("cp.async.wait_group 0;" ::: "memory");
        __syncthreads();
        if (t < NTILE - 1) { ISSUE_A(t + 1, buf ^ 1); LOAD_B(t + 1); }

        const uint32_t abase = sb + buf * BUF_BYTES;
        const uint32_t bbase = abase + B_OFF;

        // B fragments: 4 (w,hl) tiles x 2 nf-groups -> 4 js x 4 nf x 2 regs
        uint32_t bfr[4][4][2];
        #pragma unroll
        for (int js = 0; js < 4; js++)
            #pragma unroll
            for (int pr2 = 0; pr2 < 2; pr2++) {
                uint32_t tmp[4];
                ldm4(tmp, bbase +
                     ((js * 32 + pr2 * 16 + rowB) * AST + colB) * 2);
                bfr[js][pr2 * 2 + 0][0] = tmp[0];
                bfr[js][pr2 * 2 + 0][1] = tmp[1];
                bfr[js][pr2 * 2 + 1][0] = tmp[2];
                bfr[js][pr2 * 2 + 1][1] = tmp[3];
            }

        // A fragments in two waves (hi for terms 0-1, lo for term 2)
        uint32_t afr[4][4];
        #pragma unroll
        for (int p = 0; p < 4; p++)
            ldm4(afr[p], abase + (((p * 2 + 0) * 128 + rowA) * AST + colA) * 2);

        #pragma unroll
        for (int term = 0; term < 2; term++) {
            const int bhl = term;      // term0: B-hi, term1: B-lo
            #pragma unroll
            for (int pr = 0; pr < 2; pr++)
                #pragma unroll
                for (int a = 0; a < 4; a++) {
                    const int A = ap[a][pr], B = bp[a][pr];
                    #pragma unroll
                    for (int nf = 0; nf < 4; nf++)
                        mma16816(d[a][nf], afr[A], bfr[B*2+bhl][nf]);
                }
        }
        #pragma unroll
        for (int p = 0; p < 4; p++)
            ldm4(afr[p], abase + (((p * 2 + 1) * 128 + rowA) * AST + colA) * 2);
        #pragma unroll
        for (int pr = 0; pr < 2; pr++)
            #pragma unroll
            for (int a = 0; a < 4; a++) {
                const int A = ap[a][pr], B = bp[a][pr];
                #pragma unroll
                for (int nf = 0; nf < 4; nf++)
                    mma16816(d[a][nf], afr[A], bfr[B*2+0][nf]);
            }

        if (t < NTILE - 1) STORE_B(buf ^ 1);
    }

    const int bc_b = wid * 16 + (lane >> 2);
    const int l_b  = l0 + (lane & 3) * 2;
    #pragma unroll
    for (int a = 0; a < 4; a++) {
        const int comp = a >> 1;
        const long long imof = (a == 1 || a == 3) ? OUT_HALF : 0;
        const float sgn = (a == 2) ? -1.0f : 1.0f;
        #pragma unroll
        for (int nf = 0; nf < 4; nf++)
            #pragma unroll
            for (int r = 0; r < 4; r++) {
                int row = bc_b + ((r >> 1) ? 8 : 0);
                int l   = l_b + nf * 8 + (r & 1);
                long long cidx =
                    (((long long)row * 2 + comp) * LMAX + l) * MMAX + m + imof;
                if (cidx < out_floats) out[cidx] = sgn * d[a][nf][r];
            }
    }
}

// ---------------------------------------------------------------------------
extern "C" void kernel_launch(void* const* d_in, const int* in_sizes, int n_in,
                              void* d_out, int out_size) {
    const float* x = nullptr;  long long x_n = X_ELEMS;
    const float* w = nullptr;

    for (int i = 0; i < n_in; i++) {
        long long sz = (long long)in_sizes[i];
        if (sz == X_ELEMS || sz == X_ELEMS * 4) x = (const float*)d_in[i];
        else if (sz == W_ELEMS || sz == W_ELEMS * 4) w = (const float*)d_in[i];
    }
    if (!x) x = (const float*)d_in[0];
    if (!w) w = (const float*)d_in[n_in > 1 ? 1 : 0];

    long long out_floats = (long long)out_size;
    if (out_floats == OUT_BYTES_FULL) out_floats = OUT_FLOATS_FULL;
    if (out_floats <= 0 || out_floats > OUT_FLOATS_FULL)
        out_floats = OUT_FLOATS_FULL;

    static bool attr_set = false;
    if (!attr_set) {
        cudaFuncSetAttribute(gemm_kernel,
                             cudaFuncAttributeMaxDynamicSharedMemorySize,
                             SMEM_TOTAL);
        attr_set = true;
    }

    fft_kernel<<<BC * 2 * 32, 256>>>(x, x_n);
    dim3 g2(8, MMAX);
    gemm_kernel<<<g2, 256, SMEM_TOTAL>>>(w, (int)W_ELEMS,
                                         (float*)d_out, out_floats);
}

// round 13
// speedup vs baseline: 3.8481x; 1.4573x over previous
#include <cuda_runtime.h>
#include <cuda_fp16.h>
#include <cstdint>
#include <cstddef>

#define NLAT 256
#define NLON 512
#define LMAX 256
#define MMAX 257
#define BATCH 16
#define CHAN 8
#define BC (BATCH*CHAN)   /* 128 */

#define X_ELEMS  ((long long)BATCH*CHAN*2*NLAT*NLON)   /* 33,554,432  */
#define W_ELEMS  ((long long)2*MMAX*LMAX*NLAT)         /* 33,685,504  */
#define OUT_FLOATS_FULL 33685504LL
#define OUT_BYTES_FULL  134742016LL
#define OUT_HALF        16842752LL

// fp16 scratch, 67.4 MB (< 128 MiB static limit, learned R1-R4).
// Layout [plane][m][bc][k]; planes: 0=tr, 1=ti, 2=pr, 3=-pi (negated!).
__device__ __half g_f16[(size_t)4 * MMAX * BC * NLAT];

// ---------------------------------------------------------------------------
// Stage 1: batched real FFT via complex packing, radix-2 DIT, Hermitian
// unpack, scale 2*pi/512, fp16 epilogue.
// ---------------------------------------------------------------------------
__global__ __launch_bounds__(256)
void fft_kernel(const float* __restrict__ x, long long x_n) {
    __shared__ float Ar[4][513];
    __shared__ float Ai[4][513];

    const int tid  = threadIdx.x;
    const int bid  = blockIdx.x;
    const int kg   = bid & 31;
    const int comp = (bid >> 5) & 1;
    const int bc   = bid >> 6;
    const int k0   = kg * 8;

    const long long rowbase = (((long long)bc * 2 + comp) * NLAT + k0) * NLON;

    #pragma unroll
    for (int j = 0; j < 4; j++) {
        const long long ra = rowbase + (long long)(2 * j) * NLON;
        const long long rb = rowbase + (long long)(2 * j + 1) * NLON;
        for (int n = tid; n < NLON; n += 256) {
            int rv = (int)(__brev((unsigned)n) >> 23);
            long long ga = ra + n, gb = rb + n;
            Ar[j][rv] = (ga < x_n) ? x[ga] : 0.0f;
            Ai[j][rv] = (gb < x_n) ? x[gb] : 0.0f;
        }
    }
    __syncthreads();

    #pragma unroll
    for (int s = 1; s <= 9; s++) {
        const int half = 1 << (s - 1);
        const int g    = tid >> (s - 1);
        const int jj   = tid & (half - 1);
        const int base = g * (half << 1) + jj;
        const int p    = base + half;
        float si, co;
        __sincosf(-3.14159265358979323846f * (float)jj / (float)half, &si, &co);
        #pragma unroll
        for (int r = 0; r < 4; r++) {
            float ur = Ar[r][base], ui = Ai[r][base];
            float vr = Ar[r][p],    vi = Ai[r][p];
            float tr = vr * co - vi * si;
            float ti = vr * si + vi * co;
            Ar[r][base] = ur + tr;  Ai[r][base] = ui + ti;
            Ar[r][p]    = ur - tr;  Ai[r][p]    = ui - ti;
        }
        __syncthreads();
    }

    const float C   = 0.5f * 6.283185307179586f / 512.0f;
    const float IC  = comp ? -C : C;
    const int p_re  = comp * 2 + 0;
    const int p_im  = comp * 2 + 1;
    for (int idx = tid; idx < MMAX * 4; idx += 256) {
        int j = idx & 3;
        int m = idx >> 2;
        int mc = (512 - m) & 511;
        float zr = Ar[j][m],  zi = Ai[j][m];
        float cr = Ar[j][mc], ci = Ai[j][mc];
        float a_re = C  * (zr + cr);
        float a_im = IC * (zi - ci);
        float b_re = C  * (zi + ci);
        float b_im = IC * (cr - zr);

        int ka = k0 + 2 * j;
        size_t o_re = (((size_t)p_re * MMAX + m) * BC + bc) * NLAT + ka;
        size_t o_im = (((size_t)p_im * MMAX + m) * BC + bc) * NLAT + ka;

        g_f16[o_re]     = __float2half_rn(a_re);
        g_f16[o_re + 1] = __float2half_rn(b_re);
        g_f16[o_im]     = __float2half_rn(a_im);
        g_f16[o_im + 1] = __float2half_rn(b_im);
    }
}

// ---------------------------------------------------------------------------
// Stage 2: warp-level single-fp16 MMA — ONE mma per product (8 per k16).
// Accs: acc0=re0, acc1=im0, acc2=-re1, acc3=im1.
// ---------------------------------------------------------------------------
#define LT 32
#define KT 16
#define NTILE (NLAT / KT)              /* 16 */
#define AST 24                          /* 48B rows: 16B-aligned, conflict-free */
#define A_BYTES (4*128*AST*2)           /* 24576 */
#define B_OFF   A_BYTES
#define B_BYTES (2*32*AST*2)            /* 3072  */
#define BUF_BYTES (A_BYTES + B_BYTES)   /* 27648 */
#define SMEM_TOTAL (2 * BUF_BYTES)      /* 55296 = 54 KB */

__device__ __forceinline__ uint32_t smem_u32(const void* p) {
    uint32_t a;
    asm("{ .reg .u64 t; cvta.to.shared.u64 t, %1; cvt.u32.u64 %0, t; }"
        : "=r"(a) : "l"(p));
    return a;
}
__device__ __forceinline__ void cp16(uint32_t dst, const void* src) {
    asm volatile("cp.async.cg.shared.global [%0], [%1], 16;"
                 :: "r"(dst), "l"(src));
}
__device__ __forceinline__ void ldm4(uint32_t* r, uint32_t addr) {
    asm volatile("ldmatrix.sync.aligned.m8n8.x4.shared.b16 {%0,%1,%2,%3}, [%4];"
                 : "=r"(r[0]), "=r"(r[1]), "=r"(r[2]), "=r"(r[3]) : "r"(addr));
}
__device__ __forceinline__ void mma16816(float* d, const uint32_t* a,
                                         const uint32_t* b) {
    asm volatile(
        "mma.sync.aligned.m16n8k16.row.col.f32.f16.f16.f32 "
        "{%0,%1,%2,%3},{%4,%5,%6,%7},{%8,%9},{%0,%1,%2,%3};"
        : "+f"(d[0]), "+f"(d[1]), "+f"(d[2]), "+f"(d[3])
        : "r"(a[0]), "r"(a[1]), "r"(a[2]), "r"(a[3]), "r"(b[0]), "r"(b[1]));
}

__global__ __launch_bounds__(256, 2)
void gemm_kernel(const float* __restrict__ w, int w_n,
                 float* __restrict__ out, long long out_floats) {
    extern __shared__ char smem[];
    const uint32_t sb = smem_u32(smem);
    const int tid  = threadIdx.x;
    const int lane = tid & 31;
    const int wid  = tid >> 5;
    const int m    = blockIdx.y;
    const int l0   = blockIdx.x * LT;

    float d[4][4][4];
    #pragma unroll
    for (int a = 0; a < 4; a++)
        #pragma unroll
        for (int nf = 0; nf < 4; nf++)
            #pragma unroll
            for (int r = 0; r < 4; r++) d[a][nf][r] = 0.0f;

    const int rowA = wid * 16 + (lane & 7) + ((lane >> 3) & 1) * 8;
    const int colA = ((lane >> 4) & 1) * 8;
    const int rowB = (lane & 7) + ((lane >> 4) & 1) * 8;
    const int colB = ((lane >> 3) & 1) * 8;

    // B staging: 1 float4 per thread per tile (2 wpl x 32 rows x 4 float4).
    float4 bst;
    const int bj   = tid >> 7;
    const int brow = (tid >> 2) & 31;
    const int bcc  = tid & 3;

    // A cp.async: 4 x 16B chunks per thread per tile.
    // chunk c in [0,1024): ps=c>>8 (plane), row=(c>>1)&127, cc=c&1.
    #define ISSUE_A(kt, buf) do {                                              \
        _Pragma("unroll")                                                      \
        for (int i = 0; i < 4; i++) {                                          \
            int c   = i * 256 + tid;                                           \
            int ps  = c >> 8;                                                  \
            int row = (c >> 1) & 127;                                          \
            int cc  = c & 1;                                                   \
            const __half* gp = g_f16                                           \
                + (((size_t)ps * MMAX + m) * BC + row) * NLAT                  \
                + (kt) * KT + cc * 8;                                          \
            uint32_t dst = sb + (buf) * BUF_BYTES                              \
                + ((ps * 128 + row) * AST + cc * 8) * 2;                       \
            cp16(dst, gp);                                                     \
        }                                                                      \
        asm volatile("cp.async.commit_group;" ::: "memory");                   \
    } while (0)

    #define LOAD_B(kt) do {                                                    \
        int gi = ((bj * MMAX + m) * LMAX + l0 + brow) * NLAT                   \
               + (kt) * KT + bcc * 4;                                          \
        bst = (gi + 3 < w_n) ? *(const float4*)(w + gi)                        \
                             : make_float4(0.f, 0.f, 0.f, 0.f);                \
    } while (0)

    #define STORE_B(buf) do {                                                  \
        __half h0 = __float2half_rn(bst.x);                                    \
        __half h1 = __float2half_rn(bst.y);                                    \
        __half h2 = __float2half_rn(bst.z);                                    \
        __half h3 = __float2half_rn(bst.w);                                    \
        char* hb = smem + (buf) * BUF_BYTES + B_OFF                            \
            + ((bj * 32 + brow) * AST + bcc * 4) * 2;                          \
        *(__half2*)(hb + 0) = __half2(h0, h1);                                 \
        *(__half2*)(hb + 4) = __half2(h2, h3);                                 \
    } while (0)

    const int ap[4][2] = {{0,3},{1,2},{1,2},{0,3}};
    const int bp[4][2] = {{0,1},{0,1},{1,0},{1,0}};

    LOAD_B(0);
    ISSUE_A(0, 0);
    STORE_B(0);

    for (int t = 0; t < NTILE; t++) {
        const int buf = t & 1;
        asm volatile("cp.async.wait_group 0;" ::: "memory");
        __syncthreads();
        if (t < NTILE - 1) { ISSUE_A(t + 1, buf ^ 1); LOAD_B(t + 1); }

        const uint32_t abase = sb + buf * BUF_BYTES;
        const uint32_t bbase = abase + B_OFF;

        // B fragments: 2 w-planes x 4 nf x 2 regs
        uint32_t bfr[2][4][2];
        #pragma unroll
        for (int js = 0; js < 2; js++)
            #pragma unroll
            for (int pr2 = 0; pr2 < 2; pr2++) {
                uint32_t tmp[4];
                ldm4(tmp, bbase +
                     ((js * 32 + pr2 * 16 + rowB) * AST + colB) * 2);
                bfr[js][pr2 * 2 + 0][0] = tmp[0];
                bfr[js][pr2 * 2 + 0][1] = tmp[1];
                bfr[js][pr2 * 2 + 1][0] = tmp[2];
                bfr[js][pr2 * 2 + 1][1] = tmp[3];
            }

        // A fragments: 4 planes
        uint32_t afr[4][4];
        #pragma unroll
        for (int p = 0; p < 4; p++)
            ldm4(afr[p], abase + ((p * 128 + rowA) * AST + colA) * 2);

        // 32 MMAs: one per (acc, pr, nf)
        #pragma unroll
        for (int pr = 0; pr < 2; pr++)
            #pragma unroll
            for (int a = 0; a < 4; a++) {
                const int A = ap[a][pr], B = bp[a][pr];
                #pragma unroll
                for (int nf = 0; nf < 4; nf++)
                    mma16816(d[a][nf], afr[A], bfr[B][nf]);
            }

        if (t < NTILE - 1) STORE_B(buf ^ 1);
    }

    const int bc_b = wid * 16 + (lane >> 2);
    const int l_b  = l0 + (lane & 3) * 2;
    #pragma unroll
    for (int a = 0; a < 4; a++) {
        const int comp = a >> 1;
        const long long imof = (a == 1 || a == 3) ? OUT_HALF : 0;
        const float sgn = (a == 2) ? -1.0f : 1.0f;
        #pragma unroll
        for (int nf = 0; nf < 4; nf++)
            #pragma unroll
            for (int r = 0; r < 4; r++) {
                int row = bc_b + ((r >> 1) ? 8 : 0);
                int l   = l_b + nf * 8 + (r & 1);
                long long cidx =
                    (((long long)row * 2 + comp) * LMAX + l) * MMAX + m + imof;
                if (cidx < out_floats) out[cidx] = sgn * d[a][nf][r];
            }
    }
}

// ---------------------------------------------------------------------------
extern "C" void kernel_launch(void* const* d_in, const int* in_sizes, int n_in,
                              void* d_out, int out_size) {
    const float* x = nullptr;  long long x_n = X_ELEMS;
    const float* w = nullptr;

    for (int i = 0; i < n_in; i++) {
        long long sz = (long long)in_sizes[i];
        if (sz == X_ELEMS || sz == X_ELEMS * 4) x = (const float*)d_in[i];
        else if (sz == W_ELEMS || sz == W_ELEMS * 4) w = (const float*)d_in[i];
    }
    if (!x) x = (const float*)d_in[0];
    if (!w) w = (const float*)d_in[n_in > 1 ? 1 : 0];

    long long out_floats = (long long)out_size;
    if (out_floats == OUT_BYTES_FULL) out_floats = OUT_FLOATS_FULL;
    if (out_floats <= 0 || out_floats > OUT_FLOATS_FULL)
        out_floats = OUT_FLOATS_FULL;

    static bool attr_set = false;
    if (!attr_set) {
        cudaFuncSetAttribute(gemm_kernel,
                             cudaFuncAttributeMaxDynamicSharedMemorySize,
                             SMEM_TOTAL);
        attr_set = true;
    }

    fft_kernel<<<BC * 2 * 32, 256>>>(x, x_n);
    dim3 g2(8, MMAX);
    gemm_kernel<<<g2, 256, SMEM_TOTAL>>>(w, (int)W_ELEMS,
                                         (float*)d_out, out_floats);
}

// round 14
// speedup vs baseline: 4.3038x; 1.1184x over previous
#include <cuda_runtime.h>
#include <cuda_fp16.h>
#include <cstdint>
#include <cstddef>

#define NLAT 256
#define NLON 512
#define LMAX 256
#define MMAX 257
#define BATCH 16
#define CHAN 8
#define BC (BATCH*CHAN)   /* 128 */

#define X_ELEMS  ((long long)BATCH*CHAN*2*NLAT*NLON)   /* 33,554,432  */
#define W_ELEMS  ((long long)2*MMAX*LMAX*NLAT)         /* 33,685,504  */
#define OUT_FLOATS_FULL 33685504LL
#define OUT_BYTES_FULL  134742016LL
#define OUT_HALF        16842752LL

// fp16 scratch, 67.4 MB (< 128 MiB static limit, learned R1-R4).
// Layout [plane][m][bc][k]; planes: 0=tr, 1=ti, 2=pr, 3=-pi (negated!).
__device__ __half g_f16[(size_t)4 * MMAX * BC * NLAT];

// ---------------------------------------------------------------------------
// Stage 1: batched real FFT via complex packing, radix-2 DIT, Hermitian
// unpack, scale 2*pi/512, fp16 epilogue. (UNCHANGED from passing R13.)
// ---------------------------------------------------------------------------
__global__ __launch_bounds__(256)
void fft_kernel(const float* __restrict__ x, long long x_n) {
    __shared__ float Ar[4][513];
    __shared__ float Ai[4][513];

    const int tid  = threadIdx.x;
    const int bid  = blockIdx.x;
    const int kg   = bid & 31;
    const int comp = (bid >> 5) & 1;
    const int bc   = bid >> 6;
    const int k0   = kg * 8;

    const long long rowbase = (((long long)bc * 2 + comp) * NLAT + k0) * NLON;

    #pragma unroll
    for (int j = 0; j < 4; j++) {
        const long long ra = rowbase + (long long)(2 * j) * NLON;
        const long long rb = rowbase + (long long)(2 * j + 1) * NLON;
        for (int n = tid; n < NLON; n += 256) {
            int rv = (int)(__brev((unsigned)n) >> 23);
            long long ga = ra + n, gb = rb + n;
            Ar[j][rv] = (ga < x_n) ? x[ga] : 0.0f;
            Ai[j][rv] = (gb < x_n) ? x[gb] : 0.0f;
        }
    }
    __syncthreads();

    #pragma unroll
    for (int s = 1; s <= 9; s++) {
        const int half = 1 << (s - 1);
        const int g    = tid >> (s - 1);
        const int jj   = tid & (half - 1);
        const int base = g * (half << 1) + jj;
        const int p    = base + half;
        float si, co;
        __sincosf(-3.14159265358979323846f * (float)jj / (float)half, &si, &co);
        #pragma unroll
        for (int r = 0; r < 4; r++) {
            float ur = Ar[r][base], ui = Ai[r][base];
            float vr = Ar[r][p],    vi = Ai[r][p];
            float tr = vr * co - vi * si;
            float ti = vr * si + vi * co;
            Ar[r][base] = ur + tr;  Ai[r][base] = ui + ti;
            Ar[r][p]    = ur - tr;  Ai[r][p]    = ui - ti;
        }
        __syncthreads();
    }

    const float C   = 0.5f * 6.283185307179586f / 512.0f;
    const float IC  = comp ? -C : C;
    const int p_re  = comp * 2 + 0;
    const int p_im  = comp * 2 + 1;
    for (int idx = tid; idx < MMAX * 4; idx += 256) {
        int j = idx & 3;
        int m = idx >> 2;
        int mc = (512 - m) & 511;
        float zr = Ar[j][m],  zi = Ai[j][m];
        float cr = Ar[j][mc], ci = Ai[j][mc];
        float a_re = C  * (zr + cr);
        float a_im = IC * (zi - ci);
        float b_re = C  * (zi + ci);
        float b_im = IC * (cr - zr);

        int ka = k0 + 2 * j;
        size_t o_re = (((size_t)p_re * MMAX + m) * BC + bc) * NLAT + ka;
        size_t o_im = (((size_t)p_im * MMAX + m) * BC + bc) * NLAT + ka;

        g_f16[o_re]     = __float2half_rn(a_re);
        g_f16[o_re + 1] = __float2half_rn(b_re);
        g_f16[o_im]     = __float2half_rn(a_im);
        g_f16[o_im + 1] = __float2half_rn(b_im);
    }
}

// ---------------------------------------------------------------------------
// Stage 2: warp-level single-fp16 MMA, KT=32 (8 tiles): halved per-tile
// overhead, doubled cp.async overlap window. Math identical to R13.
// ---------------------------------------------------------------------------
#define LT 32
#define KT 32
#define NTILE (NLAT / KT)              /* 8 */
#define AST 40                          /* 80B rows: granules r*5%8 distinct */
#define A_BYTES (4*128*AST*2)           /* 40960 */
#define B_OFF   A_BYTES
#define B_BYTES (2*32*AST*2)            /* 5120  */
#define BUF_BYTES (A_BYTES + B_BYTES)   /* 46080 */
#define SMEM_TOTAL (2 * BUF_BYTES)      /* 92160 = 90 KB -> 2 CTAs/SM */

__device__ __forceinline__ uint32_t smem_u32(const void* p) {
    uint32_t a;
    asm("{ .reg .u64 t; cvta.to.shared.u64 t, %1; cvt.u32.u64 %0, t; }"
        : "=r"(a) : "l"(p));
    return a;
}
__device__ __forceinline__ void cp16(uint32_t dst, const void* src) {
    asm volatile("cp.async.cg.shared.global [%0], [%1], 16;"
                 :: "r"(dst), "l"(src));
}
__device__ __forceinline__ void ldm4(uint32_t* r, uint32_t addr) {
    asm volatile("ldmatrix.sync.aligned.m8n8.x4.shared.b16 {%0,%1,%2,%3}, [%4];"
                 : "=r"(r[0]), "=r"(r[1]), "=r"(r[2]), "=r"(r[3]) : "r"(addr));
}
__device__ __forceinline__ void mma16816(float* d, const uint32_t* a,
                                         const uint32_t* b) {
    asm volatile(
        "mma.sync.aligned.m16n8k16.row.col.f32.f16.f16.f32 "
        "{%0,%1,%2,%3},{%4,%5,%6,%7},{%8,%9},{%0,%1,%2,%3};"
        : "+f"(d[0]), "+f"(d[1]), "+f"(d[2]), "+f"(d[3])
        : "r"(a[0]), "r"(a[1]), "r"(a[2]), "r"(a[3]), "r"(b[0]), "r"(b[1]));
}

__global__ __launch_bounds__(256, 2)
void gemm_kernel(const float* __restrict__ w, int w_n,
                 float* __restrict__ out, long long out_floats) {
    extern __shared__ char smem[];
    const uint32_t sb = smem_u32(smem);
    const int tid  = threadIdx.x;
    const int lane = tid & 31;
    const int wid  = tid >> 5;
    const int m    = blockIdx.y;
    const int l0   = blockIdx.x * LT;

    float d[4][4][4];
    #pragma unroll
    for (int a = 0; a < 4; a++)
        #pragma unroll
        for (int nf = 0; nf < 4; nf++)
            #pragma unroll
            for (int r = 0; r < 4; r++) d[a][nf][r] = 0.0f;

    const int rowA = wid * 16 + (lane & 7) + ((lane >> 3) & 1) * 8;
    const int colA = ((lane >> 4) & 1) * 8;
    const int rowB = (lane & 7) + ((lane >> 4) & 1) * 8;
    const int colB = ((lane >> 3) & 1) * 8;

    // B staging: 2 float4 per thread per tile (2 wpl x 32 rows x 8 float4).
    float4 bst[2];
    int bj[2], brow[2], bcc[2];
    #pragma unroll
    for (int i = 0; i < 2; i++) {
        int c = i * 256 + tid;
        bj[i]   = c >> 8;
        brow[i] = (c >> 3) & 31;
        bcc[i]  = c & 7;
    }

    // A cp.async: 8 x 16B chunks per thread per tile.
    // chunk c in [0,2048): ps=c>>9 (plane), row=(c>>2)&127, cc=c&3.
    #define ISSUE_A(kt, buf) do {                                              \
        _Pragma("unroll")                                                      \
        for (int i = 0; i < 8; i++) {                                          \
            int c   = i * 256 + tid;                                           \
            int ps  = c >> 9;                                                  \
            int row = (c >> 2) & 127;                                          \
            int cc  = c & 3;                                                   \
            const __half* gp = g_f16                                           \
                + (((size_t)ps * MMAX + m) * BC + row) * NLAT                  \
                + (kt) * KT + cc * 8;                                          \
            uint32_t dst = sb + (buf) * BUF_BYTES                              \
                + ((ps * 128 + row) * AST + cc * 8) * 2;                       \
            cp16(dst, gp);                                                     \
        }                                                                      \
        asm volatile("cp.async.commit_group;" ::: "memory");                   \
    } while (0)

    #define LOAD_B(kt) do {                                                    \
        _Pragma("unroll")                                                      \
        for (int i = 0; i < 2; i++) {                                          \
            int gi = ((bj[i] * MMAX + m) * LMAX + l0 + brow[i]) * NLAT         \
                   + (kt) * KT + bcc[i] * 4;                                   \
            bst[i] = (gi + 3 < w_n) ? *(const float4*)(w + gi)                 \
                                    : make_float4(0.f, 0.f, 0.f, 0.f);         \
        }                                                                      \
    } while (0)

    #define STORE_B(buf) do {                                                  \
        _Pragma("unroll")                                                      \
        for (int i = 0; i < 2; i++) {                                          \
            __half h0 = __float2half_rn(bst[i].x);                             \
            __half h1 = __float2half_rn(bst[i].y);                             \
            __half h2 = __float2half_rn(bst[i].z);                             \
            __half h3 = __float2half_rn(bst[i].w);                             \
            char* hb = smem + (buf) * BUF_BYTES + B_OFF                        \
                + ((bj[i] * 32 + brow[i]) * AST + bcc[i] * 4) * 2;             \
            *(__half2*)(hb + 0) = __half2(h0, h1);                             \
            *(__half2*)(hb + 4) = __half2(h2, h3);                             \
        }                                                                      \
    } while (0)

    const int ap[4][2] = {{0,3},{1,2},{1,2},{0,3}};
    const int bp[4][2] = {{0,1},{0,1},{1,0},{1,0}};

    LOAD_B(0);
    ISSUE_A(0, 0);
    STORE_B(0);

    for (int t = 0; t < NTILE; t++) {
        const int buf = t & 1;
        asm volatile("cp.async.wait_group 0;" ::: "memory");
        __syncthreads();
        if (t < NTILE - 1) { ISSUE_A(t + 1, buf ^ 1); LOAD_B(t + 1); }

        const uint32_t abase = sb + buf * BUF_BYTES;
        const uint32_t bbase = abase + B_OFF;

        #pragma unroll
        for (int kc = 0; kc < 2; kc++) {
            // B fragments: 2 w-planes x 4 nf x 2 regs
            uint32_t bfr[2][4][2];
            #pragma unroll
            for (int js = 0; js < 2; js++)
                #pragma unroll
                for (int pr2 = 0; pr2 < 2; pr2++) {
                    uint32_t tmp[4];
                    ldm4(tmp, bbase +
                         ((js * 32 + pr2 * 16 + rowB) * AST + kc * 16 + colB) * 2);
                    bfr[js][pr2 * 2 + 0][0] = tmp[0];
                    bfr[js][pr2 * 2 + 0][1] = tmp[1];
                    bfr[js][pr2 * 2 + 1][0] = tmp[2];
                    bfr[js][pr2 * 2 + 1][1] = tmp[3];
                }

            // A fragments: 4 planes
            uint32_t afr[4][4];
            #pragma unroll
            for (int p = 0; p < 4; p++)
                ldm4(afr[p], abase + ((p * 128 + rowA) * AST + kc * 16 + colA) * 2);

            // 32 MMAs: one per (acc, pr, nf)
            #pragma unroll
            for (int pr = 0; pr < 2; pr++)
                #pragma unroll
                for (int a = 0; a < 4; a++) {
                    const int A = ap[a][pr], B = bp[a][pr];
                    #pragma unroll
                    for (int nf = 0; nf < 4; nf++)
                        mma16816(d[a][nf], afr[A], bfr[B][nf]);
                }
        }

        if (t < NTILE - 1) STORE_B(buf ^ 1);
    }

    const int bc_b = wid * 16 + (lane >> 2);
    const int l_b  = l0 + (lane & 3) * 2;
    #pragma unroll
    for (int a = 0; a < 4; a++) {
        const int comp = a >> 1;
        const long long imof = (a == 1 || a == 3) ? OUT_HALF : 0;
        const float sgn = (a == 2) ? -1.0f : 1.0f;
        #pragma unroll
        for (int nf = 0; nf < 4; nf++)
            #pragma unroll
            for (int r = 0; r < 4; r++) {
                int row = bc_b + ((r >> 1) ? 8 : 0);
                int l   = l_b + nf * 8 + (r & 1);
                long long cidx =
                    (((long long)row * 2 + comp) * LMAX + l) * MMAX + m + imof;
                if (cidx < out_floats) out[cidx] = sgn * d[a][nf][r];
            }
    }
}

// ---------------------------------------------------------------------------
extern "C" void kernel_launch(void* const* d_in, const int* in_sizes, int n_in,
                              void* d_out, int out_size) {
    const float* x = nullptr;  long long x_n = X_ELEMS;
    const float* w = nullptr;

    for (int i = 0; i < n_in; i++) {
        long long sz = (long long)in_sizes[i];
        if (sz == X_ELEMS || sz == X_ELEMS * 4) x = (const float*)d_in[i];
        else if (sz == W_ELEMS || sz == W_ELEMS * 4) w = (const float*)d_in[i];
    }
    if (!x) x = (const float*)d_in[0];
    if (!w) w = (const float*)d_in[n_in > 1 ? 1 : 0];

    long long out_floats = (long long)out_size;
    if (out_floats == OUT_BYTES_FULL) out_floats = OUT_FLOATS_FULL;
    if (out_floats <= 0 || out_floats > OUT_FLOATS_FULL)
        out_floats = OUT_FLOATS_FULL;

    static bool attr_set = false;
    if (!attr_set) {
        cudaFuncSetAttribute(gemm_kernel,
                             cudaFuncAttributeMaxDynamicSharedMemorySize,
                             SMEM_TOTAL);
        attr_set = true;
    }

    fft_kernel<<<BC * 2 * 32, 256>>>(x, x_n);
    dim3 g2(8, MMAX);
    gemm_kernel<<<g2, 256, SMEM_TOTAL>>>(w, (int)W_ELEMS,
                                         (float*)d_out, out_floats);
}

// round 15
// speedup vs baseline: 4.7794x; 1.1105x over previous
#include <cuda_runtime.h>
#include <cuda_fp16.h>
#include <cstdint>
#include <cstddef>

#define NLAT 256
#define NLON 512
#define LMAX 256
#define MMAX 257
#define BATCH 16
#define CHAN 8
#define BC (BATCH*CHAN)   /* 128 */

#define X_ELEMS  ((long long)BATCH*CHAN*2*NLAT*NLON)   /* 33,554,432  */
#define W_ELEMS  ((long long)2*MMAX*LMAX*NLAT)         /* 33,685,504  */
#define OUT_FLOATS_FULL 33685504LL
#define OUT_BYTES_FULL  134742016LL
#define OUT_HALF        16842752LL

// fp16 scratch, 67.4 MB (< 128 MiB static limit, learned R1-R4).
// Layout [plane][m][bc][k]; planes: 0=tr, 1=ti, 2=pr, 3=-pi (negated!).
__device__ __half g_f16[(size_t)4 * MMAX * BC * NLAT];

// Position of bin m after 4x radix-4 + 1x radix-2 DIF (digit-reversed).
__device__ __forceinline__ int perm512(int m) {
    return ((m & 3) << 7) | (((m >> 2) & 3) << 5) | (((m >> 4) & 3) << 3)
         | (((m >> 6) & 3) << 1) | ((m >> 8) & 1);
}

// ---------------------------------------------------------------------------
// Stage 1: batched real FFT via complex packing; radix-4 DIF (natural input,
// digit-reversed output read via perm512), Hermitian unpack, fp16 epilogue.
// ---------------------------------------------------------------------------
__global__ __launch_bounds__(256)
void fft_kernel(const float* __restrict__ x, long long x_n) {
    __shared__ float Ar[4][513];
    __shared__ float Ai[4][513];

    const int tid  = threadIdx.x;
    const int bid  = blockIdx.x;
    const int kg   = bid & 31;
    const int comp = (bid >> 5) & 1;
    const int bc   = bid >> 6;
    const int k0   = kg * 8;

    const long long rowbase = (((long long)bc * 2 + comp) * NLAT + k0) * NLON;

    // Natural-order load: row 2j -> real, row 2j+1 -> imag.
    #pragma unroll
    for (int j = 0; j < 4; j++) {
        const long long ra = rowbase + (long long)(2 * j) * NLON;
        const long long rb = rowbase + (long long)(2 * j + 1) * NLON;
        for (int n = tid; n < NLON; n += 256) {
            long long ga = ra + n, gb = rb + n;
            Ar[j][n] = (ga < x_n) ? x[ga] : 0.0f;
            Ai[j][n] = (gb < x_n) ? x[gb] : 0.0f;
        }
    }
    __syncthreads();

    // 4 radix-4 DIF stages: L = 512, 128, 32, 8.
    #pragma unroll
    for (int st = 0; st < 4; st++) {
        const int L = 512 >> (2 * st);
        const int q = L >> 2;
        const float wstep = -6.283185307179586f / (float)L;
        #pragma unroll
        for (int h = 0; h < 2; h++) {
            const int bf  = tid + h * 256;     // 512 butterflies (4 rows x 128)
            const int row = bf >> 7;
            const int b   = bf & 127;
            const int blk = b / q;
            const int j   = b - blk * q;
            const int i   = blk * L + j;

            float s1, c1;
            __sincosf(wstep * (float)j, &s1, &c1);
            const float c2 = c1 * c1 - s1 * s1, s2 = 2.0f * s1 * c1;
            const float c3 = c1 * c2 - s1 * s2, s3 = s1 * c2 + c1 * s2;

            float t0r = Ar[row][i],         t0i = Ai[row][i];
            float t1r = Ar[row][i + q],     t1i = Ai[row][i + q];
            float t2r = Ar[row][i + 2 * q], t2i = Ai[row][i + 2 * q];
            float t3r = Ar[row][i + 3 * q], t3i = Ai[row][i + 3 * q];

            float u0r = t0r + t2r, u0i = t0i + t2i;
            float u1r = t0r - t2r, u1i = t0i - t2i;
            float u2r = t1r + t3r, u2i = t1i + t3i;
            float u3r = t1i - t3i, u3i = t3r - t1r;   // -i*(t1-t3)

            Ar[row][i]         = u0r + u2r;
            Ai[row][i]         = u0i + u2i;
            float v1r = u1r + u3r, v1i = u1i + u3i;
            Ar[row][i + q]     = v1r * c1 - v1i * s1;
            Ai[row][i + q]     = v1r * s1 + v1i * c1;
            float v2r = u0r - u2r, v2i = u0i - u2i;
            Ar[row][i + 2 * q] = v2r * c2 - v2i * s2;
            Ai[row][i + 2 * q] = v2r * s2 + v2i * c2;
            float v3r = u1r - u3r, v3i = u1i - u3i;
            Ar[row][i + 3 * q] = v3r * c3 - v3i * s3;
            Ai[row][i + 3 * q] = v3r * s3 + v3i * c3;
        }
        __syncthreads();
    }

    // Final radix-2 stage (L=2, twiddle = 1): 1024 pairs, 4 per thread.
    #pragma unroll
    for (int h = 0; h < 4; h++) {
        const int c   = tid + h * 256;
        const int row = c >> 8;
        const int i   = (c & 255) * 2;
        float t0r = Ar[row][i],     t0i = Ai[row][i];
        float t1r = Ar[row][i + 1], t1i = Ai[row][i + 1];
        Ar[row][i]     = t0r + t1r;  Ai[row][i]     = t0i + t1i;
        Ar[row][i + 1] = t0r - t1r;  Ai[row][i + 1] = t0i - t1i;
    }
    __syncthreads();

    // Hermitian unpack (digit-reversed access) + scale + fp16 stores.
    const float C   = 0.5f * 6.283185307179586f / 512.0f;
    const float IC  = comp ? -C : C;
    const int p_re  = comp * 2 + 0;
    const int p_im  = comp * 2 + 1;
    for (int idx = tid; idx < MMAX * 4; idx += 256) {
        int j   = idx & 3;
        int m   = idx >> 2;
        int pm  = perm512(m);
        int pmc = perm512((512 - m) & 511);
        float zr = Ar[j][pm],  zi = Ai[j][pm];
        float cr = Ar[j][pmc], ci = Ai[j][pmc];
        float a_re = C  * (zr + cr);
        float a_im = IC * (zi - ci);
        float b_re = C  * (zi + ci);
        float b_im = IC * (cr - zr);

        int ka = k0 + 2 * j;
        size_t o_re = (((size_t)p_re * MMAX + m) * BC + bc) * NLAT + ka;
        size_t o_im = (((size_t)p_im * MMAX + m) * BC + bc) * NLAT + ka;

        g_f16[o_re]     = __float2half_rn(a_re);
        g_f16[o_re + 1] = __float2half_rn(b_re);
        g_f16[o_im]     = __float2half_rn(a_im);
        g_f16[o_im + 1] = __float2half_rn(b_im);
    }
}

// ---------------------------------------------------------------------------
// Stage 2: warp-level single-fp16 MMA, KT=32. (UNCHANGED from passing R14.)
// ---------------------------------------------------------------------------
#define LT 32
#define KT 32
#define NTILE (NLAT / KT)              /* 8 */
#define AST 40                          /* 80B rows: granules r*5%8 distinct */
#define A_BYTES (4*128*AST*2)           /* 40960 */
#define B_OFF   A_BYTES
#define B_BYTES (2*32*AST*2)            /* 5120  */
#define BUF_BYTES (A_BYTES + B_BYTES)   /* 46080 */
#define SMEM_TOTAL (2 * BUF_BYTES)      /* 92160 = 90 KB -> 2 CTAs/SM */

__device__ __forceinline__ uint32_t smem_u32(const void* p) {
    uint32_t a;
    asm("{ .reg .u64 t; cvta.to.shared.u64 t, %1; cvt.u32.u64 %0, t; }"
        : "=r"(a) : "l"(p));
    return a;
}
__device__ __forceinline__ void cp16(uint32_t dst, const void* src) {
    asm volatile("cp.async.cg.shared.global [%0], [%1], 16;"
                 :: "r"(dst), "l"(src));
}
__device__ __forceinline__ void ldm4(uint32_t* r, uint32_t addr) {
    asm volatile("ldmatrix.sync.aligned.m8n8.x4.shared.b16 {%0,%1,%2,%3}, [%4];"
                 : "=r"(r[0]), "=r"(r[1]), "=r"(r[2]), "=r"(r[3]) : "r"(addr));
}
__device__ __forceinline__ void mma16816(float* d, const uint32_t* a,
                                         const uint32_t* b) {
    asm volatile(
        "mma.sync.aligned.m16n8k16.row.col.f32.f16.f16.f32 "
        "{%0,%1,%2,%3},{%4,%5,%6,%7},{%8,%9},{%0,%1,%2,%3};"
        : "+f"(d[0]), "+f"(d[1]), "+f"(d[2]), "+f"(d[3])
        : "r"(a[0]), "r"(a[1]), "r"(a[2]), "r"(a[3]), "r"(b[0]), "r"(b[1]));
}

__global__ __launch_bounds__(256, 2)
void gemm_kernel(const float* __restrict__ w, int w_n,
                 float* __restrict__ out, long long out_floats) {
    extern __shared__ char smem[];
    const uint32_t sb = smem_u32(smem);
    const int tid  = threadIdx.x;
    const int lane = tid & 31;
    const int wid  = tid >> 5;
    const int m    = blockIdx.y;
    const int l0   = blockIdx.x * LT;

    float d[4][4][4];
    #pragma unroll
    for (int a = 0; a < 4; a++)
        #pragma unroll
        for (int nf = 0; nf < 4; nf++)
            #pragma unroll
            for (int r = 0; r < 4; r++) d[a][nf][r] = 0.0f;

    const int rowA = wid * 16 + (lane & 7) + ((lane >> 3) & 1) * 8;
    const int colA = ((lane >> 4) & 1) * 8;
    const int rowB = (lane & 7) + ((lane >> 4) & 1) * 8;
    const int colB = ((lane >> 3) & 1) * 8;

    float4 bst[2];
    int bj[2], brow[2], bcc[2];
    #pragma unroll
    for (int i = 0; i < 2; i++) {
        int c = i * 256 + tid;
        bj[i]   = c >> 8;
        brow[i] = (c >> 3) & 31;
        bcc[i]  = c & 7;
    }

    #define ISSUE_A(kt, buf) do {                                              \
        _Pragma("unroll")                                                      \
        for (int i = 0; i < 8; i++) {                                          \
            int c   = i * 256 + tid;                                           \
            int ps  = c >> 9;                                                  \
            int row = (c >> 2) & 127;                                          \
            int cc  = c & 3;                                                   \
            const __half* gp = g_f16                                           \
                + (((size_t)ps * MMAX + m) * BC + row) * NLAT                  \
                + (kt) * KT + cc * 8;                                          \
            uint32_t dst = sb + (buf) * BUF_BYTES                              \
                + ((ps * 128 + row) * AST + cc * 8) * 2;                       \
            cp16(dst, gp);                                                     \
        }                                                                      \
        asm volatile("cp.async.commit_group;" ::: "memory");                   \
    } while (0)

    #define LOAD_B(kt) do {                                                    \
        _Pragma("unroll")                                                      \
        for (int i = 0; i < 2; i++) {                                          \
            int gi = ((bj[i] * MMAX + m) * LMAX + l0 + brow[i]) * NLAT         \
                   + (kt) * KT + bcc[i] * 4;                                   \
            bst[i] = (gi + 3 < w_n) ? *(const float4*)(w + gi)                 \
                                    : make_float4(0.f, 0.f, 0.f, 0.f);         \
        }                                                                      \
    } while (0)

    #define STORE_B(buf) do {                                                  \
        _Pragma("unroll")                                                      \
        for (int i = 0; i < 2; i++) {                                          \
            __half h0 = __float2half_rn(bst[i].x);                             \
            __half h1 = __float2half_rn(bst[i].y);                             \
            __half h2 = __float2half_rn(bst[i].z);                             \
            __half h3 = __float2half_rn(bst[i].w);                             \
            char* hb = smem + (buf) * BUF_BYTES + B_OFF                        \
                + ((bj[i] * 32 + brow[i]) * AST + bcc[i] * 4) * 2;             \
            *(__half2*)(hb + 0) = __half2(h0, h1);                             \
            *(__half2*)(hb + 4) = __half2(h2, h3);                             \
        }                                                                      \
    } while (0)

    const int ap[4][2] = {{0,3},{1,2},{1,2},{0,3}};
    const int bp[4][2] = {{0,1},{0,1},{1,0},{1,0}};

    LOAD_B(0);
    ISSUE_A(0, 0);
    STORE_B(0);

    for (int t = 0; t < NTILE; t++) {
        const int buf = t & 1;
        asm volatile("cp.async.wait_group 0;" ::: "memory");
        __syncthreads();
        if (t < NTILE - 1) { ISSUE_A(t + 1, buf ^ 1); LOAD_B(t + 1); }

        const uint32_t abase = sb + buf * BUF_BYTES;
        const uint32_t bbase = abase + B_OFF;

        #pragma unroll
        for (int kc = 0; kc < 2; kc++) {
            uint32_t bfr[2][4][2];
            #pragma unroll
            for (int js = 0; js < 2; js++)
                #pragma unroll
                for (int pr2 = 0; pr2 < 2; pr2++) {
                    uint32_t tmp[4];
                    ldm4(tmp, bbase +
                         ((js * 32 + pr2 * 16 + rowB) * AST + kc * 16 + colB) * 2);
                    bfr[js][pr2 * 2 + 0][0] = tmp[0];
                    bfr[js][pr2 * 2 + 0][1] = tmp[1];
                    bfr[js][pr2 * 2 + 1][0] = tmp[2];
                    bfr[js][pr2 * 2 + 1][1] = tmp[3];
                }

            uint32_t afr[4][4];
            #pragma unroll
            for (int p = 0; p < 4; p++)
                ldm4(afr[p], abase + ((p * 128 + rowA) * AST + kc * 16 + colA) * 2);

            #pragma unroll
            for (int pr = 0; pr < 2; pr++)
                #pragma unroll
                for (int a = 0; a < 4; a++) {
                    const int A = ap[a][pr], B = bp[a][pr];
                    #pragma unroll
                    for (int nf = 0; nf < 4; nf++)
                        mma16816(d[a][nf], afr[A], bfr[B][nf]);
                }
        }

        if (t < NTILE - 1) STORE_B(buf ^ 1);
    }

    const int bc_b = wid * 16 + (lane >> 2);
    const int l_b  = l0 + (lane & 3) * 2;
    #pragma unroll
    for (int a = 0; a < 4; a++) {
        const int comp = a >> 1;
        const long long imof = (a == 1 || a == 3) ? OUT_HALF : 0;
        const float sgn = (a == 2) ? -1.0f : 1.0f;
        #pragma unroll
        for (int nf = 0; nf < 4; nf++)
            #pragma unroll
            for (int r = 0; r < 4; r++) {
                int row = bc_b + ((r >> 1) ? 8 : 0);
                int l   = l_b + nf * 8 + (r & 1);
                long long cidx =
                    (((long long)row * 2 + comp) * LMAX + l) * MMAX + m + imof;
                if (cidx < out_floats) out[cidx] = sgn * d[a][nf][r];
            }
    }
}

// ---------------------------------------------------------------------------
extern "C" void kernel_launch(void* const* d_in, const int* in_sizes, int n_in,
                              void* d_out, int out_size) {
    const float* x = nullptr;  long long x_n = X_ELEMS;
    const float* w = nullptr;

    for (int i = 0; i < n_in; i++) {
        long long sz = (long long)in_sizes[i];
        if (sz == X_ELEMS || sz == X_ELEMS * 4) x = (const float*)d_in[i];
        else if (sz == W_ELEMS || sz == W_ELEMS * 4) w = (const float*)d_in[i];
    }
    if (!x) x = (const float*)d_in[0];
    if (!w) w = (const float*)d_in[n_in > 1 ? 1 : 0];

    long long out_floats = (long long)out_size;
    if (out_floats == OUT_BYTES_FULL) out_floats = OUT_FLOATS_FULL;
    if (out_floats <= 0 || out_floats > OUT_FLOATS_FULL)
        out_floats = OUT_FLOATS_FULL;

    static bool attr_set = false;
    if (!attr_set) {
        cudaFuncSetAttribute(gemm_kernel,
                             cudaFuncAttributeMaxDynamicSharedMemorySize,
                             SMEM_TOTAL);
        attr_set = true;
    }

    fft_kernel<<<BC * 2 * 32, 256>>>(x, x_n);
    dim3 g2(8, MMAX);
    gemm_kernel<<<g2, 256, SMEM_TOTAL>>>(w, (int)W_ELEMS,
                                         (float*)d_out, out_floats);
}

// round 17
// speedup vs baseline: 5.2453x; 1.0975x over previous
#include <cuda_runtime.h>
#include <cuda_fp16.h>
#include <cstdint>
#include <cstddef>

#define NLAT 256
#define NLON 512
#define LMAX 256
#define MMAX 257
#define BATCH 16
#define CHAN 8
#define BC (BATCH*CHAN)   /* 128 */

#define X_ELEMS  ((long long)BATCH*CHAN*2*NLAT*NLON)   /* 33,554,432  */
#define W_ELEMS  ((long long)2*MMAX*LMAX*NLAT)         /* 33,685,504  */
#define OUT_FLOATS_FULL 33685504LL
#define OUT_BYTES_FULL  134742016LL
#define OUT_HALF        16842752LL

// fp16 scratch, 67.4 MB (< 128 MiB static limit, learned R1-R4).
// Layout [plane][m][bc][k]; planes: 0=tr, 1=ti, 2=pr, 3=-pi (negated!).
__device__ __half g_f16[(size_t)4 * MMAX * BC * NLAT];

// Position of bin m after 4x radix-4 + 1x radix-2 DIF (digit-reversed).
__device__ __forceinline__ int perm512(int m) {
    return ((m & 3) << 7) | (((m >> 2) & 3) << 5) | (((m >> 4) & 3) << 3)
         | (((m >> 6) & 3) << 1) | ((m >> 8) & 1);
}

// ---------------------------------------------------------------------------
// Stage 1: batched real FFT via complex packing; radix-4 DIF.
// R16: 16 k-rows (8 packed cFFTs) per block -> 4 independent butterflies
// per thread per stage (ILP to hide LDS latency); 4096 blocks.
// ---------------------------------------------------------------------------
__global__ __launch_bounds__(256)
void fft_kernel(const float* __restrict__ x, long long x_n) {
    __shared__ float Ar[8][513];
    __shared__ float Ai[8][513];

    const int tid  = threadIdx.x;
    const int bid  = blockIdx.x;
    const int kg   = bid & 15;
    const int comp = (bid >> 4) & 1;
    const int bc   = bid >> 5;
    const int k0   = kg * 16;

    const long long rowbase = (((long long)bc * 2 + comp) * NLAT + k0) * NLON;

    // Natural-order load: cFFT row j packs k-rows (2j, 2j+1).
    #pragma unroll
    for (int j = 0; j < 8; j++) {
        const long long ra = rowbase + (long long)(2 * j) * NLON;
        const long long rb = rowbase + (long long)(2 * j + 1) * NLON;
        for (int n = tid; n < NLON; n += 256) {
            long long ga = ra + n, gb = rb + n;
            Ar[j][n] = (ga < x_n) ? x[ga] : 0.0f;
            Ai[j][n] = (gb < x_n) ? x[gb] : 0.0f;
        }
    }
    __syncthreads();

    // 4 radix-4 DIF stages: L = 512, 128, 32, 8. 1024 butterflies/stage.
    #pragma unroll
    for (int st = 0; st < 4; st++) {
        const int L = 512 >> (2 * st);
        const int q = L >> 2;
        const float wstep = -6.283185307179586f / (float)L;
        #pragma unroll
        for (int h = 0; h < 4; h++) {
            const int bf  = tid + h * 256;     // 1024 butterflies (8 rows x 128)
            const int row = bf >> 7;
            const int b   = bf & 127;
            const int blk = b / q;
            const int j   = b - blk * q;
            const int i   = blk * L + j;

            float s1, c1;
            __sincosf(wstep * (float)j, &s1, &c1);
            const float c2 = c1 * c1 - s1 * s1, s2 = 2.0f * s1 * c1;
            const float c3 = c1 * c2 - s1 * s2, s3 = s1 * c2 + c1 * s2;

            float t0r = Ar[row][i],         t0i = Ai[row][i];
            float t1r = Ar[row][i + q],     t1i = Ai[row][i + q];
            float t2r = Ar[row][i + 2 * q], t2i = Ai[row][i + 2 * q];
            float t3r = Ar[row][i + 3 * q], t3i = Ai[row][i + 3 * q];

            float u0r = t0r + t2r, u0i = t0i + t2i;
            float u1r = t0r - t2r, u1i = t0i - t2i;
            float u2r = t1r + t3r, u2i = t1i + t3i;
            float u3r = t1i - t3i, u3i = t3r - t1r;   // -i*(t1-t3)

            Ar[row][i]         = u0r + u2r;
            Ai[row][i]         = u0i + u2i;
            float v1r = u1r + u3r, v1i = u1i + u3i;
            Ar[row][i + q]     = v1r * c1 - v1i * s1;
            Ai[row][i + q]     = v1r * s1 + v1i * c1;
            float v2r = u0r - u2r, v2i = u0i - u2i;
            Ar[row][i + 2 * q] = v2r * c2 - v2i * s2;
            Ai[row][i + 2 * q] = v2r * s2 + v2i * c2;
            float v3r = u1r - u3r, v3i = u1i - u3i;
            Ar[row][i + 3 * q] = v3r * c3 - v3i * s3;
            Ai[row][i + 3 * q] = v3r * s3 + v3i * c3;
        }
        __syncthreads();
    }

    // Final radix-2 stage (L=2, twiddle = 1): 2048 pairs, 8 per thread.
    #pragma unroll
    for (int h = 0; h < 8; h++) {
        const int c   = tid + h * 256;
        const int row = c >> 8;
        const int i   = (c & 255) * 2;
        float t0r = Ar[row][i],     t0i = Ai[row][i];
        float t1r = Ar[row][i + 1], t1i = Ai[row][i + 1];
        Ar[row][i]     = t0r + t1r;  Ai[row][i]     = t0i + t1i;
        Ar[row][i + 1] = t0r - t1r;  Ai[row][i + 1] = t0i - t1i;
    }
    __syncthreads();

    // Hermitian unpack (digit-reversed access) + scale + fp16 stores.
    const float C   = 0.5f * 6.283185307179586f / 512.0f;
    const float IC  = comp ? -C : C;
    const int p_re  = comp * 2 + 0;
    const int p_im  = comp * 2 + 1;
    for (int idx = tid; idx < MMAX * 8; idx += 256) {
        int j   = idx & 7;
        int m   = idx >> 3;
        int pm  = perm512(m);
        int pmc = perm512((512 - m) & 511);
        float zr = Ar[j][pm],  zi = Ai[j][pm];
        float cr = Ar[j][pmc], ci = Ai[j][pmc];
        float a_re = C  * (zr + cr);
        float a_im = IC * (zi - ci);
        float b_re = C  * (zi + ci);
        float b_im = IC * (cr - zr);

        int ka = k0 + 2 * j;
        size_t o_re = (((size_t)p_re * MMAX + m) * BC + bc) * NLAT + ka;
        size_t o_im = (((size_t)p_im * MMAX + m) * BC + bc) * NLAT + ka;

        g_f16[o_re]     = __float2half_rn(a_re);
        g_f16[o_re + 1] = __float2half_rn(b_re);
        g_f16[o_im]     = __float2half_rn(a_im);
        g_f16[o_im + 1] = __float2half_rn(b_im);
    }
}

// ---------------------------------------------------------------------------
// Stage 2: warp-level single-fp16 MMA, KT=32. (UNCHANGED from passing R15.)
// ---------------------------------------------------------------------------
#define LT 32
#define KT 32
#define NTILE (NLAT / KT)              /* 8 */
#define AST 40                          /* 80B rows: granules r*5%8 distinct */
#define A_BYTES (4*128*AST*2)           /* 40960 */
#define B_OFF   A_BYTES
#define B_BYTES (2*32*AST*2)            /* 5120  */
#define BUF_BYTES (A_BYTES + B_BYTES)   /* 46080 */
#define SMEM_TOTAL (2 * BUF_BYTES)      /* 92160 = 90 KB -> 2 CTAs/SM */

__device__ __forceinline__ uint32_t smem_u32(const void* p) {
    uint32_t a;
    asm("{ .reg .u64 t; cvta.to.shared.u64 t, %1; cvt.u32.u64 %0, t; }"
        : "=r"(a) : "l"(p));
    return a;
}
__device__ __forceinline__ void cp16(uint32_t dst, const void* src) {
    asm volatile("cp.async.cg.shared.global [%0], [%1], 16;"
                 :: "r"(dst), "l"(src));
}
__device__ __forceinline__ void ldm4(uint32_t* r, uint32_t addr) {
    asm volatile("ldmatrix.sync.aligned.m8n8.x4.shared.b16 {%0,%1,%2,%3}, [%4];"
                 : "=r"(r[0]), "=r"(r[1]), "=r"(r[2]), "=r"(r[3]) : "r"(addr));
}
__device__ __forceinline__ void mma16816(float* d, const uint32_t* a,
                                         const uint32_t* b) {
    asm volatile(
        "mma.sync.aligned.m16n8k16.row.col.f32.f16.f16.f32 "
        "{%0,%1,%2,%3},{%4,%5,%6,%7},{%8,%9},{%0,%1,%2,%3};"
        : "+f"(d[0]), "+f"(d[1]), "+f"(d[2]), "+f"(d[3])
        : "r"(a[0]), "r"(a[1]), "r"(a[2]), "r"(a[3]), "r"(b[0]), "r"(b[1]));
}

__global__ __launch_bounds__(256, 2)
void gemm_kernel(const float* __restrict__ w, int w_n,
                 float* __restrict__ out, long long out_floats) {
    extern __shared__ char smem[];
    const uint32_t sb = smem_u32(smem);
    const int tid  = threadIdx.x;
    const int lane = tid & 31;
    const int wid  = tid >> 5;
    const int m    = blockIdx.y;
    const int l0   = blockIdx.x * LT;

    float d[4][4][4];
    #pragma unroll
    for (int a = 0; a < 4; a++)
        #pragma unroll
        for (int nf = 0; nf < 4; nf++)
            #pragma unroll
            for (int r = 0; r < 4; r++) d[a][nf][r] = 0.0f;

    const int rowA = wid * 16 + (lane & 7) + ((lane >> 3) & 1) * 8;
    const int colA = ((lane >> 4) & 1) * 8;
    const int rowB = (lane & 7) + ((lane >> 4) & 1) * 8;
    const int colB = ((lane >> 3) & 1) * 8;

    float4 bst[2];
    int bj[2], brow[2], bcc[2];
    #pragma unroll
    for (int i = 0; i < 2; i++) {
        int c = i * 256 + tid;
        bj[i]   = c >> 8;
        brow[i] = (c >> 3) & 31;
        bcc[i]  = c & 7;
    }

    #define ISSUE_A(kt, buf) do {                                              \
        _Pragma("unroll")                                                      \
        for (int i = 0; i < 8; i++) {                                          \
            int c   = i * 256 + tid;                                           \
            int ps  = c >> 9;                                                  \
            int row = (c >> 2) & 127;                                          \
            int cc  = c & 3;                                                   \
            const __half* gp = g_f16                                           \
                + (((size_t)ps * MMAX + m) * BC + row) * NLAT                  \
                + (kt) * KT + cc * 8;                                          \
            uint32_t dst = sb + (buf) * BUF_BYTES                              \
                + ((ps * 128 + row) * AST + cc * 8) * 2;                       \
            cp16(dst, gp);                                                     \
        }                                                                      \
        asm volatile("cp.async.commit_group;" ::: "memory");                   \
    } while (0)

    #define LOAD_B(kt) do {                                                    \
        _Pragma("unroll")                                                      \
        for (int i = 0; i < 2; i++) {                                          \
            int gi = ((bj[i] * MMAX + m) * LMAX + l0 + brow[i]) * NLAT         \
                   + (kt) * KT + bcc[i] * 4;                                   \
            bst[i] = (gi + 3 < w_n) ? *(const float4*)(w + gi)                 \
                                    : make_float4(0.f, 0.f, 0.f, 0.f);         \
        }                                                                      \
    } while (0)

    #define STORE_B(buf) do {                                                  \
        _Pragma("unroll")                                                      \
        for (int i = 0; i < 2; i++) {                                          \
            __half h0 = __float2half_rn(bst[i].x);                             \
            __half h1 = __float2half_rn(bst[i].y);                             \
            __half h2 = __float2half_rn(bst[i].z);                             \
            __half h3 = __float2half_rn(bst[i].w);                             \
            char* hb = smem + (buf) * BUF_BYTES + B_OFF                        \
                + ((bj[i] * 32 + brow[i]) * AST + bcc[i] * 4) * 2;             \
            *(__half2*)(hb + 0) = __half2(h0, h1);                             \
            *(__half2*)(hb + 4) = __half2(h2, h3);                             \
        }                                                                      \
    } while (0)

    const int ap[4][2] = {{0,3},{1,2},{1,2},{0,3}};
    const int bp[4][2] = {{0,1},{0,1},{1,0},{1,0}};

    LOAD_B(0);
    ISSUE_A(0, 0);
    STORE_B(0);

    for (int t = 0; t < NTILE; t++) {
        const int buf = t & 1;
        asm volatile("cp.async.wait_group 0;" ::: "memory");
        __syncthreads();
        if (t < NTILE - 1) { ISSUE_A(t + 1, buf ^ 1); LOAD_B(t + 1); }

        const uint32_t abase = sb + buf * BUF_BYTES;
        const uint32_t bbase = abase + B_OFF;

        #pragma unroll
        for (int kc = 0; kc < 2; kc++) {
            uint32_t bfr[2][4][2];
            #pragma unroll
            for (int js = 0; js < 2; js++)
                #pragma unroll
                for (int pr2 = 0; pr2 < 2; pr2++) {
                    uint32_t tmp[4];
                    ldm4(tmp, bbase +
                         ((js * 32 + pr2 * 16 + rowB) * AST + kc * 16 + colB) * 2);
                    bfr[js][pr2 * 2 + 0][0] = tmp[0];
                    bfr[js][pr2 * 2 + 0][1] = tmp[1];
                    bfr[js][pr2 * 2 + 1][0] = tmp[2];
                    bfr[js][pr2 * 2 + 1][1] = tmp[3];
                }

            uint32_t afr[4][4];
            #pragma unroll
            for (int p = 0; p < 4; p++)
                ldm4(afr[p], abase + ((p * 128 + rowA) * AST + kc * 16 + colA) * 2);

            #pragma unroll
            for (int pr = 0; pr < 2; pr++)
                #pragma unroll
                for (int a = 0; a < 4; a++) {
                    const int A = ap[a][pr], B = bp[a][pr];
                    #pragma unroll
                    for (int nf = 0; nf < 4; nf++)
                        mma16816(d[a][nf], afr[A], bfr[B][nf]);
                }
        }

        if (t < NTILE - 1) STORE_B(buf ^ 1);
    }

    const int bc_b = wid * 16 + (lane >> 2);
    const int l_b  = l0 + (lane & 3) * 2;
    #pragma unroll
    for (int a = 0; a < 4; a++) {
        const int comp = a >> 1;
        const long long imof = (a == 1 || a == 3) ? OUT_HALF : 0;
        const float sgn = (a == 2) ? -1.0f : 1.0f;
        #pragma unroll
        for (int nf = 0; nf < 4; nf++)
            #pragma unroll
            for (int r = 0; r < 4; r++) {
                int row = bc_b + ((r >> 1) ? 8 : 0);
                int l   = l_b + nf * 8 + (r & 1);
                long long cidx =
                    (((long long)row * 2 + comp) * LMAX + l) * MMAX + m + imof;
                if (cidx < out_floats) out[cidx] = sgn * d[a][nf][r];
            }
    }
}

// ---------------------------------------------------------------------------
extern "C" void kernel_launch(void* const* d_in, const int* in_sizes, int n_in,
                              void* d_out, int out_size) {
    const float* x = nullptr;  long long x_n = X_ELEMS;
    const float* w = nullptr;

    for (int i = 0; i < n_in; i++) {
        long long sz = (long long)in_sizes[i];
        if (sz == X_ELEMS || sz == X_ELEMS * 4) x = (const float*)d_in[i];
        else if (sz == W_ELEMS || sz == W_ELEMS * 4) w = (const float*)d_in[i];
    }
    if (!x) x = (const float*)d_in[0];
    if (!w) w = (const float*)d_in[n_in > 1 ? 1 : 0];

    long long out_floats = (long long)out_size;
    if (out_floats == OUT_BYTES_FULL) out_floats = OUT_FLOATS_FULL;
    if (out_floats <= 0 || out_floats > OUT_FLOATS_FULL)
        out_floats = OUT_FLOATS_FULL;

    static bool attr_set = false;
    if (!attr_set) {
        cudaFuncSetAttribute(gemm_kernel,
                             cudaFuncAttributeMaxDynamicSharedMemorySize,
                             SMEM_TOTAL);
        attr_set = true;
    }

    fft_kernel<<<BC * 2 * 16, 256>>>(x, x_n);
    dim3 g2(8, MMAX);
    gemm_kernel<<<g2, 256, SMEM_TOTAL>>>(w, (int)W_ELEMS,
                                         (float*)d_out, out_floats);
}